// round 13
// baseline (speedup 1.0000x reference)
#include <cuda_runtime.h>
#include <cuda_bf16.h>

#define BATCH 2
#define SEQ   2048
#define FEAT  1024
#define NH    16
#define HD    64
#define MTOT  (BATCH*SEQ)     // 4096
#define BHT   (BATCH*NH)      // 32
#define GK    2048            // complex-concat K dim

// ---------------- scratch (static device globals; no allocation) ----------
__device__ unsigned short g_Xhi[MTOT*GK];            // bf16 hi of [xr|xi] / attn out
__device__ unsigned short g_Xlo[MTOT*GK];            // bf16 lo
__device__ unsigned short g_Whi[8192*GK];            // W^T K-major: QKV 0..6143, O 6144..8191
__device__ unsigned short g_Wlo[8192*GK];
__device__ float g_bias[8192];

// Q packed [hi_ri(128) | hi_ri(128) | lo_ri(128)], K packed [hi | lo | hi]
__device__ unsigned short g_Qp[(size_t)BHT*SEQ*384];
__device__ unsigned short g_Kp[(size_t)BHT*SEQ*384];
__device__ float          g_V [(size_t)BHT*SEQ*128];   // [bh][s][r(64)|i(64)] fp32
__device__ unsigned short g_VThi[(size_t)BHT*128*SEQ]; // [bh][d(r|i)][s]
__device__ unsigned short g_VTlo[(size_t)BHT*128*SEQ];
__device__ float          g_S  [(size_t)BHT*SEQ*SEQ];  // scores fp32, 512 MB
__device__ unsigned short g_Phi[(size_t)BHT*SEQ*SEQ];  // softmax hi, 256 MB
__device__ unsigned short g_Plo[(size_t)BHT*SEQ*SEQ];  // softmax lo, 256 MB

// ---------------------------- helpers --------------------------------------
__device__ __forceinline__ unsigned smem_u32(const void* p) {
    unsigned a;
    asm("{ .reg .u64 t; cvta.to.shared.u64 t, %1; cvt.u32.u64 %0, t; }"
        : "=r"(a) : "l"(p));
    return a;
}
__device__ __forceinline__ void ldm_x4(unsigned* r, unsigned addr) {
    asm volatile("ldmatrix.sync.aligned.m8n8.x4.shared.b16 {%0,%1,%2,%3}, [%4];"
                 : "=r"(r[0]), "=r"(r[1]), "=r"(r[2]), "=r"(r[3]) : "r"(addr));
}
__device__ __forceinline__ void mma_bf16(float* c, const unsigned* a,
                                         unsigned b0, unsigned b1) {
    asm volatile(
        "mma.sync.aligned.m16n8k16.row.col.f32.bf16.bf16.f32 "
        "{%0,%1,%2,%3}, {%4,%5,%6,%7}, {%8,%9}, {%0,%1,%2,%3};"
        : "+f"(c[0]), "+f"(c[1]), "+f"(c[2]), "+f"(c[3])
        : "r"(a[0]), "r"(a[1]), "r"(a[2]), "r"(a[3]), "r"(b0), "r"(b1));
}
// split two fp32 into packed bf16 hi-pair and lo-pair
__device__ __forceinline__ void split2(float x, float y, unsigned& hi, unsigned& lo) {
    __nv_bfloat16 hx = __float2bfloat16(x), hy = __float2bfloat16(y);
    float rx = x - __bfloat162float(hx), ry = y - __bfloat162float(hy);
    __nv_bfloat16 lx = __float2bfloat16(rx), ly = __float2bfloat16(ry);
    hi = ((unsigned)__bfloat16_as_ushort(hy) << 16) | __bfloat16_as_ushort(hx);
    lo = ((unsigned)__bfloat16_as_ushort(ly) << 16) | __bfloat16_as_ushort(lx);
}
// one k32 chunk of the 128x128 warp-tiled mma core (shared by all GEMMs).
// A and B fragments both via ldmatrix.x4 (B: 4 matrices = b0/b1 for nj, nj+1).
__device__ __forceinline__ void gemm_chunk(unsigned sAu, unsigned sBu,
                                           int wm, int wn, int lane,
                                           float acc[2][8][4]) {
    const int mtx  = lane >> 3;     // 0..3: which 8x8 matrix this lane addresses
    const int rowi = lane & 7;
    #pragma unroll
    for (int s = 0; s < 2; s++) {
        unsigned afr[2][4];
        #pragma unroll
        for (int mi = 0; mi < 2; mi++) {
            unsigned addr = sAu + (wm*32 + mi*16 + (lane & 15))*80
                          + ((lane >> 4)*8 + s*16)*2;
            ldm_x4(afr[mi], addr);
        }
        unsigned bfr[8][2];
        #pragma unroll
        for (int np = 0; np < 4; np++) {     // nj pair {2*np, 2*np+1}
            unsigned r[4];
            unsigned addr = sBu
                + (wn*64 + np*16 + ((mtx >> 1) << 3) + rowi)*80
                + (s*16 + ((mtx & 1) << 3))*2;
            ldm_x4(r, addr);
            bfr[np*2+0][0] = r[0]; bfr[np*2+0][1] = r[1];
            bfr[np*2+1][0] = r[2]; bfr[np*2+1][1] = r[3];
        }
        #pragma unroll
        for (int mi = 0; mi < 2; mi++)
            #pragma unroll
            for (int nj = 0; nj < 8; nj++)
                mma_bf16(acc[mi][nj], afr[mi], bfr[nj][0], bfr[nj][1]);
    }
}

// ---------------------------------------------------------------------------
// pack_x: fp32 x_r/x_i -> bf16 hi/lo [MTOT, GK]
// ---------------------------------------------------------------------------
__global__ void pack_x(const float* __restrict__ xr, const float* __restrict__ xi)
{
    int idx = blockIdx.x * 256 + threadIdx.x;
    int m = idx >> 11, n = idx & 2047;
    float v = (n < 1024) ? xr[(size_t)m*1024 + n] : xi[(size_t)m*1024 + n - 1024];
    __nv_bfloat16 hi = __float2bfloat16(v);
    float lo = v - __bfloat162float(hi);
    g_Xhi[idx] = __bfloat16_as_ushort(hi);
    g_Xlo[idx] = __bfloat16_as_ushort(__float2bfloat16(lo));
}

// ---------------------------------------------------------------------------
// pack_w: W^T (K-major) with complex block signs at row n_offset.
// ---------------------------------------------------------------------------
__global__ void pack_w(const float* __restrict__ Wr, const float* __restrict__ Wi,
                       int n_offset)
{
    __shared__ float s[32*33];
    const int t = threadIdx.x;
    const int nl0 = blockIdx.x << 5;
    const int k0  = blockIdx.y << 5;
    const int comp = nl0 >> 10;
    const int j0 = nl0 & 1023;

    const float* src; float sgn = 1.0f; int kr0;
    if (k0 < 1024) { kr0 = k0; src = comp ? Wi : Wr; }
    else { kr0 = k0 - 1024; if (comp) src = Wr; else { src = Wi; sgn = -1.0f; } }

    #pragma unroll
    for (int p = 0; p < 4; p++) {
        int e = p*256 + t, kr = e >> 5, jc = e & 31;
        s[kr*33 + jc] = src[(size_t)(kr0 + kr)*1024 + j0 + jc] * sgn;
    }
    __syncthreads();
    #pragma unroll
    for (int p = 0; p < 4; p++) {
        int e = p*256 + t, nr = e >> 5, kc = e & 31;
        float v = s[kc*33 + nr];
        __nv_bfloat16 hi = __float2bfloat16(v);
        float lo = v - __bfloat162float(hi);
        size_t o = (size_t)(n_offset + nl0 + nr)*GK + k0 + kc;
        g_Whi[o] = __bfloat16_as_ushort(hi);
        g_Wlo[o] = __bfloat16_as_ushort(__float2bfloat16(lo));
    }
}

__global__ void pack_bias(const float* __restrict__ br, const float* __restrict__ bi,
                          int off)
{
    int n = blockIdx.x * 256 + threadIdx.x;
    g_bias[off + n] = (n < 1024) ? br[n] : bi[n - 1024];
}

// ---------------------------------------------------------------------------
// tgemm: split-bf16 HMMA GEMM over K=2048, 3 passes (hi*hi, hi*lo, lo*hi).
// MODE 0 (QKV): Q -> g_Qp [hi|hi|lo], K -> g_Kp [hi|lo|hi], V fp32.
// MODE 1 (O):   write fp32 to Cout split by comp.
// ---------------------------------------------------------------------------
template<int MODE>
__global__ void __launch_bounds__(256, 2) tgemm(float* __restrict__ Cout, int nb_off)
{
    __shared__ __align__(16) __nv_bfloat16 sA[2][128*40];
    __shared__ __align__(16) __nv_bfloat16 sB[2][128*40];

    const int t    = threadIdx.x;
    const int lane = t & 31;
    const int wid  = t >> 5;
    const int wm   = wid & 3;
    const int wn   = wid >> 2;
    const int m0   = blockIdx.y << 7;
    const int n0   = blockIdx.x << 7;

    const char* Ahi = (const char*)g_Xhi;
    const char* Alo = (const char*)g_Xlo;
    const char* Bhi = (const char*)(g_Whi + (size_t)nb_off*GK);
    const char* Blo = (const char*)(g_Wlo + (size_t)nb_off*GK);

    float acc[2][8][4];
    #pragma unroll
    for (int i = 0; i < 2; i++)
        #pragma unroll
        for (int j = 0; j < 8; j++)
            #pragma unroll
            for (int q = 0; q < 4; q++) acc[i][j][q] = 0.f;

    const unsigned sAb = smem_u32(&sA[0][0]);
    const unsigned sBb = smem_u32(&sB[0][0]);
    const int rrow = t >> 2, rc = (t & 3) << 4;

    {
        const char* Ap = Ahi + (size_t)m0*(GK*2);
        const char* Bp = Bhi + (size_t)n0*(GK*2);
        uint4 a0 = *(const uint4*)(Ap + (size_t)rrow*(GK*2) + rc);
        uint4 a1 = *(const uint4*)(Ap + (size_t)(rrow+64)*(GK*2) + rc);
        uint4 b0 = *(const uint4*)(Bp + (size_t)rrow*(GK*2) + rc);
        uint4 b1 = *(const uint4*)(Bp + (size_t)(rrow+64)*(GK*2) + rc);
        *(uint4*)((char*)&sA[0][0] + rrow*80 + rc)      = a0;
        *(uint4*)((char*)&sA[0][0] + (rrow+64)*80 + rc) = a1;
        *(uint4*)((char*)&sB[0][0] + rrow*80 + rc)      = b0;
        *(uint4*)((char*)&sB[0][0] + (rrow+64)*80 + rc) = b1;
    }
    __syncthreads();

    for (int cc = 0; cc < 192; cc++) {
        const int buf = cc & 1;
        uint4 pa0, pa1, pb0, pb1;
        const bool pf = (cc + 1 < 192);
        if (pf) {
            const int nc = cc + 1, pass = nc >> 6, kt = (nc & 63) << 5;
            const char* Ap = (pass == 2 ? Alo : Ahi) + (size_t)m0*(GK*2) + kt*2;
            const char* Bp = (pass == 1 ? Blo : Bhi) + (size_t)n0*(GK*2) + kt*2;
            pa0 = *(const uint4*)(Ap + (size_t)rrow*(GK*2) + rc);
            pa1 = *(const uint4*)(Ap + (size_t)(rrow+64)*(GK*2) + rc);
            pb0 = *(const uint4*)(Bp + (size_t)rrow*(GK*2) + rc);
            pb1 = *(const uint4*)(Bp + (size_t)(rrow+64)*(GK*2) + rc);
        }
        gemm_chunk(sAb + buf*10240, sBb + buf*10240, wm, wn, lane, acc);
        if (pf) {
            const int nb = buf ^ 1;
            *(uint4*)((char*)&sA[nb][0] + rrow*80 + rc)      = pa0;
            *(uint4*)((char*)&sA[nb][0] + (rrow+64)*80 + rc) = pa1;
            *(uint4*)((char*)&sB[nb][0] + rrow*80 + rc)      = pb0;
            *(uint4*)((char*)&sB[nb][0] + (rrow+64)*80 + rc) = pb1;
        }
        __syncthreads();
    }

    const int r0 = m0 + wm*32 + (lane >> 2);
    const int cb = wn*64 + ((lane & 3) << 1);
    #pragma unroll
    for (int mi = 0; mi < 2; mi++)
        #pragma unroll
        for (int nj = 0; nj < 8; nj++) {
            const int n = n0 + cb + nj*8;
            const float bx = g_bias[nb_off + n];
            const float by = g_bias[nb_off + n + 1];
            float2 v0 = make_float2(acc[mi][nj][0] + bx, acc[mi][nj][1] + by);
            float2 v1 = make_float2(acc[mi][nj][2] + bx, acc[mi][nj][3] + by);
            const int row = r0 + mi*16;
            if (MODE == 0) {
                const int proj = n >> 11, rem = n & 2047;
                const int comp = rem >> 10, j = rem & 1023;
                const int h = j >> 6, d = j & 63;
                #pragma unroll
                for (int rr = 0; rr < 2; rr++) {
                    const int rw = row + rr*8;
                    const float2 v = rr ? v1 : v0;
                    const int bh = (rw >> 11)*NH + h, sq = rw & 2047;
                    if (proj == 0) {          // Q: [hi | hi | lo]
                        unsigned hi, lo; split2(v.x, v.y, hi, lo);
                        size_t base = ((size_t)bh*SEQ + sq)*384 + comp*64 + d;
                        *(unsigned*)(g_Qp + base)       = hi;
                        *(unsigned*)(g_Qp + base + 128) = hi;
                        *(unsigned*)(g_Qp + base + 256) = lo;
                    } else if (proj == 1) {   // K: [hi | lo | hi]
                        unsigned hi, lo; split2(v.x, v.y, hi, lo);
                        size_t base = ((size_t)bh*SEQ + sq)*384 + comp*64 + d;
                        *(unsigned*)(g_Kp + base)       = hi;
                        *(unsigned*)(g_Kp + base + 128) = lo;
                        *(unsigned*)(g_Kp + base + 256) = hi;
                    } else {
                        *(float2*)(g_V + ((size_t)bh*SEQ + sq)*128 + comp*64 + d) = v;
                    }
                }
            } else {
                const int comp = n >> 10, j = n & 1023;
                float* dst = Cout + (size_t)comp*((size_t)MTOT*FEAT) + j;
                *(float2*)(dst + (size_t)row*FEAT)     = v0;
                *(float2*)(dst + (size_t)(row+8)*FEAT) = v1;
            }
        }
}

// ---------------------------------------------------------------------------
// pack_vt: g_V [bh][s][128] fp32 -> transposed bf16 hi/lo [bh][d128][s]
// ---------------------------------------------------------------------------
__global__ void pack_vt()
{
    __shared__ float sm[32*33];
    const int t = threadIdx.x;
    const int bh = blockIdx.z;
    const int c0 = blockIdx.y << 5;   // d-col tile (0..127)
    const int s0 = blockIdx.x << 5;   // seq tile

    #pragma unroll
    for (int p = 0; p < 4; p++) {
        int e = p*256 + t, r = e >> 5, c = e & 31;
        sm[r*33 + c] = g_V[((size_t)bh*SEQ + s0 + r)*128 + c0 + c];
    }
    __syncthreads();
    #pragma unroll
    for (int p = 0; p < 4; p++) {
        int e = p*256 + t, r = e >> 5, c = e & 31;   // r: d-local, c: s-local
        float v = sm[c*33 + r];
        __nv_bfloat16 hi = __float2bfloat16(v);
        float lo = v - __bfloat162float(hi);
        size_t o = ((size_t)bh*128 + c0 + r)*SEQ + s0 + c;
        g_VThi[o] = __bfloat16_as_ushort(hi);
        g_VTlo[o] = __bfloat16_as_ushort(__float2bfloat16(lo));
    }
}

// ---------------------------------------------------------------------------
// scores_mma: S = 0.125 * Q'.K'^T over K=384
//   Q'=[Qhi|Qhi|Qlo], K'=[Khi|Klo|Khi] -> Qhi.Khi + Qhi.Klo + Qlo.Khi
// ---------------------------------------------------------------------------
__global__ void __launch_bounds__(256, 2) scores_mma(const float* __restrict__ mask)
{
    __shared__ __align__(16) __nv_bfloat16 sA[2][128*40];
    __shared__ __align__(16) __nv_bfloat16 sB[2][128*40];

    const int t    = threadIdx.x;
    const int lane = t & 31;
    const int wid  = t >> 5;
    const int wm   = wid & 3;
    const int wn   = wid >> 2;
    const int bh   = blockIdx.z;
    const int m0   = blockIdx.y << 7;
    const int n0   = blockIdx.x << 7;

    const char* Ap0 = (const char*)(g_Qp + ((size_t)bh*SEQ + m0)*384);
    const char* Bp0 = (const char*)(g_Kp + ((size_t)bh*SEQ + n0)*384);

    float acc[2][8][4];
    #pragma unroll
    for (int i = 0; i < 2; i++)
        #pragma unroll
        for (int j = 0; j < 8; j++)
            #pragma unroll
            for (int q = 0; q < 4; q++) acc[i][j][q] = 0.f;

    const unsigned sAb = smem_u32(&sA[0][0]);
    const unsigned sBb = smem_u32(&sB[0][0]);
    const int rrow = t >> 2, rc = (t & 3) << 4;

    {
        uint4 a0 = *(const uint4*)(Ap0 + (size_t)rrow*768 + rc);
        uint4 a1 = *(const uint4*)(Ap0 + (size_t)(rrow+64)*768 + rc);
        uint4 b0 = *(const uint4*)(Bp0 + (size_t)rrow*768 + rc);
        uint4 b1 = *(const uint4*)(Bp0 + (size_t)(rrow+64)*768 + rc);
        *(uint4*)((char*)&sA[0][0] + rrow*80 + rc)      = a0;
        *(uint4*)((char*)&sA[0][0] + (rrow+64)*80 + rc) = a1;
        *(uint4*)((char*)&sB[0][0] + rrow*80 + rc)      = b0;
        *(uint4*)((char*)&sB[0][0] + (rrow+64)*80 + rc) = b1;
    }
    __syncthreads();

    for (int cc = 0; cc < 12; cc++) {
        const int buf = cc & 1;
        uint4 pa0, pa1, pb0, pb1;
        const bool pf = (cc + 1 < 12);
        if (pf) {
            const int ko = (cc + 1) << 6;   // byte offset (32 bf16 per chunk)
            pa0 = *(const uint4*)(Ap0 + (size_t)rrow*768 + ko + rc);
            pa1 = *(const uint4*)(Ap0 + (size_t)(rrow+64)*768 + ko + rc);
            pb0 = *(const uint4*)(Bp0 + (size_t)rrow*768 + ko + rc);
            pb1 = *(const uint4*)(Bp0 + (size_t)(rrow+64)*768 + ko + rc);
        }
        gemm_chunk(sAb + buf*10240, sBb + buf*10240, wm, wn, lane, acc);
        if (pf) {
            const int nb = buf ^ 1;
            *(uint4*)((char*)&sA[nb][0] + rrow*80 + rc)      = pa0;
            *(uint4*)((char*)&sA[nb][0] + (rrow+64)*80 + rc) = pa1;
            *(uint4*)((char*)&sB[nb][0] + rrow*80 + rc)      = pb0;
            *(uint4*)((char*)&sB[nb][0] + (rrow+64)*80 + rc) = pb1;
        }
        __syncthreads();
    }

    const int b = bh >> 4;
    const int r0 = m0 + wm*32 + (lane >> 2);
    const int cb = wn*64 + ((lane & 3) << 1);
    #pragma unroll
    for (int mi = 0; mi < 2; mi++)
        #pragma unroll
        for (int nj = 0; nj < 8; nj++) {
            const int n = n0 + cb + nj*8;
            const float mkx = (1.0f - mask[b*SEQ + n])   * -1e9f;
            const float mky = (1.0f - mask[b*SEQ + n+1]) * -1e9f;
            const int row = r0 + mi*16;
            float2 v0 = make_float2(acc[mi][nj][0]*0.125f + mkx,
                                    acc[mi][nj][1]*0.125f + mky);
            float2 v1 = make_float2(acc[mi][nj][2]*0.125f + mkx,
                                    acc[mi][nj][3]*0.125f + mky);
            *(float2*)(g_S + ((size_t)bh*SEQ + row)*SEQ + n)     = v0;
            *(float2*)(g_S + ((size_t)bh*SEQ + row + 8)*SEQ + n) = v1;
        }
}

// ---------------------------------------------------------------------------
// softmax: row softmax of g_S -> bf16 hi/lo P buffers
// ---------------------------------------------------------------------------
__global__ void __launch_bounds__(256) softmax_kernel()
{
    const size_t roff = (size_t)blockIdx.x * SEQ;
    const float* p = g_S + roff;
    const int t = threadIdx.x;
    float v[8];
    float mx = -1e30f;
    #pragma unroll
    for (int i = 0; i < 8; i++) { v[i] = p[t + (i << 8)]; mx = fmaxf(mx, v[i]); }
    #pragma unroll
    for (int o = 16; o > 0; o >>= 1) mx = fmaxf(mx, __shfl_xor_sync(0xffffffffu, mx, o));
    __shared__ float redm[8];
    __shared__ float reds[8];
    if ((t & 31) == 0) redm[t >> 5] = mx;
    __syncthreads();
    mx = redm[0];
    #pragma unroll
    for (int i = 1; i < 8; i++) mx = fmaxf(mx, redm[i]);

    float sum = 0.f;
    #pragma unroll
    for (int i = 0; i < 8; i++) { v[i] = __expf(v[i] - mx); sum += v[i]; }
    #pragma unroll
    for (int o = 16; o > 0; o >>= 1) sum += __shfl_xor_sync(0xffffffffu, sum, o);
    if ((t & 31) == 0) reds[t >> 5] = sum;
    __syncthreads();
    sum = 0.f;
    #pragma unroll
    for (int i = 0; i < 8; i++) sum += reds[i];
    const float inv = 1.0f / sum;
    #pragma unroll
    for (int i = 0; i < 8; i++) {
        float pv = v[i] * inv;
        __nv_bfloat16 hi = __float2bfloat16(pv);
        float lo = pv - __bfloat162float(hi);
        g_Phi[roff + t + (i << 8)] = __bfloat16_as_ushort(hi);
        g_Plo[roff + t + (i << 8)] = __bfloat16_as_ushort(__float2bfloat16(lo));
    }
}

// ---------------------------------------------------------------------------
// pv_mma: out = Phi.Vhi + Phi.Vlo + Plo.Vhi  (M=128 tile, N=128, K=2048 x3)
// Writes o-proj input g_Xhi/g_Xlo directly: col = comp*1024 + h*64 + d.
// ---------------------------------------------------------------------------
__global__ void __launch_bounds__(256, 2) pv_mma()
{
    __shared__ __align__(16) __nv_bfloat16 sA[2][128*40];
    __shared__ __align__(16) __nv_bfloat16 sB[2][128*40];

    const int t    = threadIdx.x;
    const int lane = t & 31;
    const int wid  = t >> 5;
    const int wm   = wid & 3;
    const int wn   = wid >> 2;
    const int bh   = blockIdx.z;
    const int m0   = blockIdx.y << 7;

    const char* Phi = (const char*)(g_Phi + ((size_t)bh*SEQ + m0)*SEQ);
    const char* Plo = (const char*)(g_Plo + ((size_t)bh*SEQ + m0)*SEQ);
    const char* Vhi = (const char*)(g_VThi + (size_t)bh*128*SEQ);
    const char* Vlo = (const char*)(g_VTlo + (size_t)bh*128*SEQ);

    float acc[2][8][4];
    #pragma unroll
    for (int i = 0; i < 2; i++)
        #pragma unroll
        for (int j = 0; j < 8; j++)
            #pragma unroll
            for (int q = 0; q < 4; q++) acc[i][j][q] = 0.f;

    const unsigned sAb = smem_u32(&sA[0][0]);
    const unsigned sBb = smem_u32(&sB[0][0]);
    const int rrow = t >> 2, rc = (t & 3) << 4;

    {
        uint4 a0 = *(const uint4*)(Phi + (size_t)rrow*(SEQ*2) + rc);
        uint4 a1 = *(const uint4*)(Phi + (size_t)(rrow+64)*(SEQ*2) + rc);
        uint4 b0 = *(const uint4*)(Vhi + (size_t)rrow*(SEQ*2) + rc);
        uint4 b1 = *(const uint4*)(Vhi + (size_t)(rrow+64)*(SEQ*2) + rc);
        *(uint4*)((char*)&sA[0][0] + rrow*80 + rc)      = a0;
        *(uint4*)((char*)&sA[0][0] + (rrow+64)*80 + rc) = a1;
        *(uint4*)((char*)&sB[0][0] + rrow*80 + rc)      = b0;
        *(uint4*)((char*)&sB[0][0] + (rrow+64)*80 + rc) = b1;
    }
    __syncthreads();

    for (int cc = 0; cc < 192; cc++) {
        const int buf = cc & 1;
        uint4 pa0, pa1, pb0, pb1;
        const bool pf = (cc + 1 < 192);
        if (pf) {
            const int nc = cc + 1, pass = nc >> 6, kt = (nc & 63) << 5;
            const char* Ap = (pass == 2 ? Plo : Phi) + kt*2;
            const char* Bp = (pass == 1 ? Vlo : Vhi) + kt*2;
            pa0 = *(const uint4*)(Ap + (size_t)rrow*(SEQ*2) + rc);
            pa1 = *(const uint4*)(Ap + (size_t)(rrow+64)*(SEQ*2) + rc);
            pb0 = *(const uint4*)(Bp + (size_t)rrow*(SEQ*2) + rc);
            pb1 = *(const uint4*)(Bp + (size_t)(rrow+64)*(SEQ*2) + rc);
        }
        gemm_chunk(sAb + buf*10240, sBb + buf*10240, wm, wn, lane, acc);
        if (pf) {
            const int nb = buf ^ 1;
            *(uint4*)((char*)&sA[nb][0] + rrow*80 + rc)      = pa0;
            *(uint4*)((char*)&sA[nb][0] + (rrow+64)*80 + rc) = pa1;
            *(uint4*)((char*)&sB[nb][0] + rrow*80 + rc)      = pb0;
            *(uint4*)((char*)&sB[nb][0] + (rrow+64)*80 + rc) = pb1;
        }
        __syncthreads();
    }

    const int b = bh >> 4, h = bh & 15;
    const int r0 = m0 + wm*32 + (lane >> 2);
    const int cb = wn*64 + ((lane & 3) << 1);
    #pragma unroll
    for (int mi = 0; mi < 2; mi++)
        #pragma unroll
        for (int nj = 0; nj < 8; nj++) {
            const int n = cb + nj*8;                 // 0..127
            const int comp = n >> 6, d = n & 63;
            const int col = comp*1024 + h*64 + d;
            const int row = r0 + mi*16;
            #pragma unroll
            for (int rr = 0; rr < 2; rr++) {
                const float x = acc[mi][nj][rr*2 + 0];
                const float y = acc[mi][nj][rr*2 + 1];
                unsigned hi, lo; split2(x, y, hi, lo);
                size_t base = (size_t)(b*SEQ + row + rr*8)*GK + col;
                *(unsigned*)(g_Xhi + base) = hi;
                *(unsigned*)(g_Xlo + base) = lo;
            }
        }
}

// ---------------------------------------------------------------------------
extern "C" void kernel_launch(void* const* d_in, const int* in_sizes, int n_in,
                              void* d_out, int out_size)
{
    (void)in_sizes; (void)n_in; (void)out_size;
    const float* x_r  = (const float*)d_in[0];
    const float* x_i  = (const float*)d_in[1];
    const float* mask = (const float*)d_in[2];
    const float* Wq_r = (const float*)d_in[3];
    const float* Wq_i = (const float*)d_in[4];
    const float* bq_r = (const float*)d_in[5];
    const float* bq_i = (const float*)d_in[6];
    const float* Wk_r = (const float*)d_in[7];
    const float* Wk_i = (const float*)d_in[8];
    const float* bk_r = (const float*)d_in[9];
    const float* bk_i = (const float*)d_in[10];
    const float* Wv_r = (const float*)d_in[11];
    const float* Wv_i = (const float*)d_in[12];
    const float* bv_r = (const float*)d_in[13];
    const float* bv_i = (const float*)d_in[14];
    const float* Wo_r = (const float*)d_in[15];
    const float* Wo_i = (const float*)d_in[16];
    const float* bo_r = (const float*)d_in[17];
    const float* bo_i = (const float*)d_in[18];
    float* out = (float*)d_out;

    pack_x<<<MTOT*GK/256, 256>>>(x_r, x_i);
    pack_w<<<dim3(64, 64), 256>>>(Wq_r, Wq_i, 0);
    pack_w<<<dim3(64, 64), 256>>>(Wk_r, Wk_i, 2048);
    pack_w<<<dim3(64, 64), 256>>>(Wv_r, Wv_i, 4096);
    pack_w<<<dim3(64, 64), 256>>>(Wo_r, Wo_i, 6144);
    pack_bias<<<8, 256>>>(bq_r, bq_i, 0);
    pack_bias<<<8, 256>>>(bk_r, bk_i, 2048);
    pack_bias<<<8, 256>>>(bv_r, bv_i, 4096);
    pack_bias<<<8, 256>>>(bo_r, bo_i, 6144);

    // QKV projection (HMMA) -> packed Q/K bf16 (384-dim), V fp32
    tgemm<0><<<dim3(48, 32), 256>>>(nullptr, 0);
    pack_vt<<<dim3(SEQ/32, 4, BHT), 256>>>();

    // attention on HMMA
    scores_mma<<<dim3(SEQ/128, SEQ/128, BHT), 256>>>(mask);
    softmax_kernel<<<BHT*SEQ, 256>>>();
    pv_mma<<<dim3(1, SEQ/128, BHT), 256>>>();

    // output projection (HMMA) -> d_out
    tgemm<1><<<dim3(16, 32), 256>>>(out, 6144);
}

// round 14
// speedup vs baseline: 1.0033x; 1.0033x over previous
#include <cuda_runtime.h>
#include <cuda_bf16.h>

#define BATCH 2
#define SEQ   2048
#define FEAT  1024
#define NH    16
#define HD    64
#define MTOT  (BATCH*SEQ)     // 4096
#define BHT   (BATCH*NH)      // 32
#define GK    2048            // complex-concat K dim

// ---------------- scratch (static device globals; no allocation) ----------
__device__ unsigned short g_Xhi[MTOT*GK];            // bf16 hi of [xr|xi] / attn out
__device__ unsigned short g_Xlo[MTOT*GK];            // bf16 lo
__device__ unsigned short g_Whi[8192*GK];            // W^T K-major: QKV 0..6143, O 6144..8191
__device__ unsigned short g_Wlo[8192*GK];
__device__ float g_bias[8192];

// Q packed [hi_ri(128) | hi_ri(128) | lo_ri(128)], K packed [hi | lo | hi]
__device__ unsigned short g_Qp[(size_t)BHT*SEQ*384];
__device__ unsigned short g_Kp[(size_t)BHT*SEQ*384];
__device__ float          g_V [(size_t)BHT*SEQ*128];   // [bh][s][r(64)|i(64)] fp32
__device__ unsigned short g_VThi[(size_t)BHT*128*SEQ]; // [bh][d(r|i)][s]
__device__ unsigned short g_VTlo[(size_t)BHT*128*SEQ];
__device__ float          g_S  [(size_t)BHT*SEQ*SEQ];  // scores fp32, 512 MB
__device__ unsigned short g_Phi[(size_t)BHT*SEQ*SEQ];  // softmax hi, 256 MB
__device__ unsigned short g_Plo[(size_t)BHT*SEQ*SEQ];  // softmax lo, 256 MB

// ---------------------------- helpers --------------------------------------
__device__ __forceinline__ unsigned smem_u32(const void* p) {
    unsigned a;
    asm("{ .reg .u64 t; cvta.to.shared.u64 t, %1; cvt.u32.u64 %0, t; }"
        : "=r"(a) : "l"(p));
    return a;
}
__device__ __forceinline__ void ldm_x4(unsigned* r, unsigned addr) {
    asm volatile("ldmatrix.sync.aligned.m8n8.x4.shared.b16 {%0,%1,%2,%3}, [%4];"
                 : "=r"(r[0]), "=r"(r[1]), "=r"(r[2]), "=r"(r[3]) : "r"(addr));
}
__device__ __forceinline__ void mma_bf16(float* c, const unsigned* a,
                                         unsigned b0, unsigned b1) {
    asm volatile(
        "mma.sync.aligned.m16n8k16.row.col.f32.bf16.bf16.f32 "
        "{%0,%1,%2,%3}, {%4,%5,%6,%7}, {%8,%9}, {%0,%1,%2,%3};"
        : "+f"(c[0]), "+f"(c[1]), "+f"(c[2]), "+f"(c[3])
        : "r"(a[0]), "r"(a[1]), "r"(a[2]), "r"(a[3]), "r"(b0), "r"(b1));
}
// split two fp32 into packed bf16 hi-pair and lo-pair
__device__ __forceinline__ void split2(float x, float y, unsigned& hi, unsigned& lo) {
    __nv_bfloat16 hx = __float2bfloat16(x), hy = __float2bfloat16(y);
    float rx = x - __bfloat162float(hx), ry = y - __bfloat162float(hy);
    __nv_bfloat16 lx = __float2bfloat16(rx), ly = __float2bfloat16(ry);
    hi = ((unsigned)__bfloat16_as_ushort(hy) << 16) | __bfloat16_as_ushort(hx);
    lo = ((unsigned)__bfloat16_as_ushort(ly) << 16) | __bfloat16_as_ushort(lx);
}
// one k32 chunk of the 128x128 warp-tiled mma core (shared by all GEMMs).
// A and B fragments both via ldmatrix.x4 (B: 4 matrices = b0/b1 for nj, nj+1).
__device__ __forceinline__ void gemm_chunk(unsigned sAu, unsigned sBu,
                                           int wm, int wn, int lane,
                                           float acc[2][8][4]) {
    const int mtx  = lane >> 3;     // 0..3: which 8x8 matrix this lane addresses
    const int rowi = lane & 7;
    #pragma unroll
    for (int s = 0; s < 2; s++) {
        unsigned afr[2][4];
        #pragma unroll
        for (int mi = 0; mi < 2; mi++) {
            unsigned addr = sAu + (wm*32 + mi*16 + (lane & 15))*80
                          + ((lane >> 4)*8 + s*16)*2;
            ldm_x4(afr[mi], addr);
        }
        unsigned bfr[8][2];
        #pragma unroll
        for (int np = 0; np < 4; np++) {     // nj pair {2*np, 2*np+1}
            unsigned r[4];
            unsigned addr = sBu
                + (wn*64 + np*16 + ((mtx >> 1) << 3) + rowi)*80
                + (s*16 + ((mtx & 1) << 3))*2;
            ldm_x4(r, addr);
            bfr[np*2+0][0] = r[0]; bfr[np*2+0][1] = r[1];
            bfr[np*2+1][0] = r[2]; bfr[np*2+1][1] = r[3];
        }
        #pragma unroll
        for (int mi = 0; mi < 2; mi++)
            #pragma unroll
            for (int nj = 0; nj < 8; nj++)
                mma_bf16(acc[mi][nj], afr[mi], bfr[nj][0], bfr[nj][1]);
    }
}

// ---------------------------------------------------------------------------
// pack_x: fp32 x_r/x_i -> bf16 hi/lo [MTOT, GK]
// ---------------------------------------------------------------------------
__global__ void pack_x(const float* __restrict__ xr, const float* __restrict__ xi)
{
    int idx = blockIdx.x * 256 + threadIdx.x;
    int m = idx >> 11, n = idx & 2047;
    float v = (n < 1024) ? xr[(size_t)m*1024 + n] : xi[(size_t)m*1024 + n - 1024];
    __nv_bfloat16 hi = __float2bfloat16(v);
    float lo = v - __bfloat162float(hi);
    g_Xhi[idx] = __bfloat16_as_ushort(hi);
    g_Xlo[idx] = __bfloat16_as_ushort(__float2bfloat16(lo));
}

// ---------------------------------------------------------------------------
// pack_w: W^T (K-major) with complex block signs at row n_offset.
// ---------------------------------------------------------------------------
__global__ void pack_w(const float* __restrict__ Wr, const float* __restrict__ Wi,
                       int n_offset)
{
    __shared__ float s[32*33];
    const int t = threadIdx.x;
    const int nl0 = blockIdx.x << 5;
    const int k0  = blockIdx.y << 5;
    const int comp = nl0 >> 10;
    const int j0 = nl0 & 1023;

    const float* src; float sgn = 1.0f; int kr0;
    if (k0 < 1024) { kr0 = k0; src = comp ? Wi : Wr; }
    else { kr0 = k0 - 1024; if (comp) src = Wr; else { src = Wi; sgn = -1.0f; } }

    #pragma unroll
    for (int p = 0; p < 4; p++) {
        int e = p*256 + t, kr = e >> 5, jc = e & 31;
        s[kr*33 + jc] = src[(size_t)(kr0 + kr)*1024 + j0 + jc] * sgn;
    }
    __syncthreads();
    #pragma unroll
    for (int p = 0; p < 4; p++) {
        int e = p*256 + t, nr = e >> 5, kc = e & 31;
        float v = s[kc*33 + nr];
        __nv_bfloat16 hi = __float2bfloat16(v);
        float lo = v - __bfloat162float(hi);
        size_t o = (size_t)(n_offset + nl0 + nr)*GK + k0 + kc;
        g_Whi[o] = __bfloat16_as_ushort(hi);
        g_Wlo[o] = __bfloat16_as_ushort(__float2bfloat16(lo));
    }
}

__global__ void pack_bias(const float* __restrict__ br, const float* __restrict__ bi,
                          int off)
{
    int n = blockIdx.x * 256 + threadIdx.x;
    g_bias[off + n] = (n < 1024) ? br[n] : bi[n - 1024];
}

// ---------------------------------------------------------------------------
// tgemm: split-bf16 HMMA GEMM over K=2048, 3 passes (hi*hi, hi*lo, lo*hi).
// MODE 0 (QKV): Q -> g_Qp [hi|hi|lo], K -> g_Kp [hi|lo|hi], V fp32.
// MODE 1 (O):   write fp32 to Cout split by comp.
// ---------------------------------------------------------------------------
template<int MODE>
__global__ void __launch_bounds__(256, 2) tgemm(float* __restrict__ Cout, int nb_off)
{
    __shared__ __align__(16) __nv_bfloat16 sA[2][128*40];
    __shared__ __align__(16) __nv_bfloat16 sB[2][128*40];

    const int t    = threadIdx.x;
    const int lane = t & 31;
    const int wid  = t >> 5;
    const int wm   = wid & 3;
    const int wn   = wid >> 2;
    const int m0   = blockIdx.y << 7;
    const int n0   = blockIdx.x << 7;

    const char* Ahi = (const char*)g_Xhi;
    const char* Alo = (const char*)g_Xlo;
    const char* Bhi = (const char*)(g_Whi + (size_t)nb_off*GK);
    const char* Blo = (const char*)(g_Wlo + (size_t)nb_off*GK);

    float acc[2][8][4];
    #pragma unroll
    for (int i = 0; i < 2; i++)
        #pragma unroll
        for (int j = 0; j < 8; j++)
            #pragma unroll
            for (int q = 0; q < 4; q++) acc[i][j][q] = 0.f;

    const unsigned sAb = smem_u32(&sA[0][0]);
    const unsigned sBb = smem_u32(&sB[0][0]);
    const int rrow = t >> 2, rc = (t & 3) << 4;

    {
        const char* Ap = Ahi + (size_t)m0*(GK*2);
        const char* Bp = Bhi + (size_t)n0*(GK*2);
        uint4 a0 = *(const uint4*)(Ap + (size_t)rrow*(GK*2) + rc);
        uint4 a1 = *(const uint4*)(Ap + (size_t)(rrow+64)*(GK*2) + rc);
        uint4 b0 = *(const uint4*)(Bp + (size_t)rrow*(GK*2) + rc);
        uint4 b1 = *(const uint4*)(Bp + (size_t)(rrow+64)*(GK*2) + rc);
        *(uint4*)((char*)&sA[0][0] + rrow*80 + rc)      = a0;
        *(uint4*)((char*)&sA[0][0] + (rrow+64)*80 + rc) = a1;
        *(uint4*)((char*)&sB[0][0] + rrow*80 + rc)      = b0;
        *(uint4*)((char*)&sB[0][0] + (rrow+64)*80 + rc) = b1;
    }
    __syncthreads();

    for (int cc = 0; cc < 192; cc++) {
        const int buf = cc & 1;
        uint4 pa0, pa1, pb0, pb1;
        const bool pf = (cc + 1 < 192);
        if (pf) {
            const int nc = cc + 1, pass = nc >> 6, kt = (nc & 63) << 5;
            const char* Ap = (pass == 2 ? Alo : Ahi) + (size_t)m0*(GK*2) + kt*2;
            const char* Bp = (pass == 1 ? Blo : Bhi) + (size_t)n0*(GK*2) + kt*2;
            pa0 = *(const uint4*)(Ap + (size_t)rrow*(GK*2) + rc);
            pa1 = *(const uint4*)(Ap + (size_t)(rrow+64)*(GK*2) + rc);
            pb0 = *(const uint4*)(Bp + (size_t)rrow*(GK*2) + rc);
            pb1 = *(const uint4*)(Bp + (size_t)(rrow+64)*(GK*2) + rc);
        }
        gemm_chunk(sAb + buf*10240, sBb + buf*10240, wm, wn, lane, acc);
        if (pf) {
            const int nb = buf ^ 1;
            *(uint4*)((char*)&sA[nb][0] + rrow*80 + rc)      = pa0;
            *(uint4*)((char*)&sA[nb][0] + (rrow+64)*80 + rc) = pa1;
            *(uint4*)((char*)&sB[nb][0] + rrow*80 + rc)      = pb0;
            *(uint4*)((char*)&sB[nb][0] + (rrow+64)*80 + rc) = pb1;
        }
        __syncthreads();
    }

    const int r0 = m0 + wm*32 + (lane >> 2);
    const int cb = wn*64 + ((lane & 3) << 1);
    #pragma unroll
    for (int mi = 0; mi < 2; mi++)
        #pragma unroll
        for (int nj = 0; nj < 8; nj++) {
            const int n = n0 + cb + nj*8;
            const float bx = g_bias[nb_off + n];
            const float by = g_bias[nb_off + n + 1];
            float2 v0 = make_float2(acc[mi][nj][0] + bx, acc[mi][nj][1] + by);
            float2 v1 = make_float2(acc[mi][nj][2] + bx, acc[mi][nj][3] + by);
            const int row = r0 + mi*16;
            if (MODE == 0) {
                const int proj = n >> 11, rem = n & 2047;
                const int comp = rem >> 10, j = rem & 1023;
                const int h = j >> 6, d = j & 63;
                #pragma unroll
                for (int rr = 0; rr < 2; rr++) {
                    const int rw = row + rr*8;
                    const float2 v = rr ? v1 : v0;
                    const int bh = (rw >> 11)*NH + h, sq = rw & 2047;
                    if (proj == 0) {          // Q: [hi | hi | lo]
                        unsigned hi, lo; split2(v.x, v.y, hi, lo);
                        size_t base = ((size_t)bh*SEQ + sq)*384 + comp*64 + d;
                        *(unsigned*)(g_Qp + base)       = hi;
                        *(unsigned*)(g_Qp + base + 128) = hi;
                        *(unsigned*)(g_Qp + base + 256) = lo;
                    } else if (proj == 1) {   // K: [hi | lo | hi]
                        unsigned hi, lo; split2(v.x, v.y, hi, lo);
                        size_t base = ((size_t)bh*SEQ + sq)*384 + comp*64 + d;
                        *(unsigned*)(g_Kp + base)       = hi;
                        *(unsigned*)(g_Kp + base + 128) = lo;
                        *(unsigned*)(g_Kp + base + 256) = hi;
                    } else {
                        *(float2*)(g_V + ((size_t)bh*SEQ + sq)*128 + comp*64 + d) = v;
                    }
                }
            } else {
                const int comp = n >> 10, j = n & 1023;
                float* dst = Cout + (size_t)comp*((size_t)MTOT*FEAT) + j;
                *(float2*)(dst + (size_t)row*FEAT)     = v0;
                *(float2*)(dst + (size_t)(row+8)*FEAT) = v1;
            }
        }
}

// ---------------------------------------------------------------------------
// pack_vt: g_V [bh][s][128] fp32 -> transposed bf16 hi/lo [bh][d128][s]
// ---------------------------------------------------------------------------
__global__ void pack_vt()
{
    __shared__ float sm[32*33];
    const int t = threadIdx.x;
    const int bh = blockIdx.z;
    const int c0 = blockIdx.y << 5;   // d-col tile (0..127)
    const int s0 = blockIdx.x << 5;   // seq tile

    #pragma unroll
    for (int p = 0; p < 4; p++) {
        int e = p*256 + t, r = e >> 5, c = e & 31;
        sm[r*33 + c] = g_V[((size_t)bh*SEQ + s0 + r)*128 + c0 + c];
    }
    __syncthreads();
    #pragma unroll
    for (int p = 0; p < 4; p++) {
        int e = p*256 + t, r = e >> 5, c = e & 31;   // r: d-local, c: s-local
        float v = sm[c*33 + r];
        __nv_bfloat16 hi = __float2bfloat16(v);
        float lo = v - __bfloat162float(hi);
        size_t o = ((size_t)bh*128 + c0 + r)*SEQ + s0 + c;
        g_VThi[o] = __bfloat16_as_ushort(hi);
        g_VTlo[o] = __bfloat16_as_ushort(__float2bfloat16(lo));
    }
}

// ---------------------------------------------------------------------------
// scores_mma: S = 0.125 * Q'.K'^T over K=384
//   Q'=[Qhi|Qhi|Qlo], K'=[Khi|Klo|Khi] -> Qhi.Khi + Qhi.Klo + Qlo.Khi
// ---------------------------------------------------------------------------
__global__ void __launch_bounds__(256, 2) scores_mma(const float* __restrict__ mask)
{
    __shared__ __align__(16) __nv_bfloat16 sA[2][128*40];
    __shared__ __align__(16) __nv_bfloat16 sB[2][128*40];

    const int t    = threadIdx.x;
    const int lane = t & 31;
    const int wid  = t >> 5;
    const int wm   = wid & 3;
    const int wn   = wid >> 2;
    const int bh   = blockIdx.z;
    const int m0   = blockIdx.y << 7;
    const int n0   = blockIdx.x << 7;

    const char* Ap0 = (const char*)(g_Qp + ((size_t)bh*SEQ + m0)*384);
    const char* Bp0 = (const char*)(g_Kp + ((size_t)bh*SEQ + n0)*384);

    float acc[2][8][4];
    #pragma unroll
    for (int i = 0; i < 2; i++)
        #pragma unroll
        for (int j = 0; j < 8; j++)
            #pragma unroll
            for (int q = 0; q < 4; q++) acc[i][j][q] = 0.f;

    const unsigned sAb = smem_u32(&sA[0][0]);
    const unsigned sBb = smem_u32(&sB[0][0]);
    const int rrow = t >> 2, rc = (t & 3) << 4;

    {
        uint4 a0 = *(const uint4*)(Ap0 + (size_t)rrow*768 + rc);
        uint4 a1 = *(const uint4*)(Ap0 + (size_t)(rrow+64)*768 + rc);
        uint4 b0 = *(const uint4*)(Bp0 + (size_t)rrow*768 + rc);
        uint4 b1 = *(const uint4*)(Bp0 + (size_t)(rrow+64)*768 + rc);
        *(uint4*)((char*)&sA[0][0] + rrow*80 + rc)      = a0;
        *(uint4*)((char*)&sA[0][0] + (rrow+64)*80 + rc) = a1;
        *(uint4*)((char*)&sB[0][0] + rrow*80 + rc)      = b0;
        *(uint4*)((char*)&sB[0][0] + (rrow+64)*80 + rc) = b1;
    }
    __syncthreads();

    for (int cc = 0; cc < 12; cc++) {
        const int buf = cc & 1;
        uint4 pa0, pa1, pb0, pb1;
        const bool pf = (cc + 1 < 12);
        if (pf) {
            const int ko = (cc + 1) << 6;   // byte offset (32 bf16 per chunk)
            pa0 = *(const uint4*)(Ap0 + (size_t)rrow*768 + ko + rc);
            pa1 = *(const uint4*)(Ap0 + (size_t)(rrow+64)*768 + ko + rc);
            pb0 = *(const uint4*)(Bp0 + (size_t)rrow*768 + ko + rc);
            pb1 = *(const uint4*)(Bp0 + (size_t)(rrow+64)*768 + ko + rc);
        }
        gemm_chunk(sAb + buf*10240, sBb + buf*10240, wm, wn, lane, acc);
        if (pf) {
            const int nb = buf ^ 1;
            *(uint4*)((char*)&sA[nb][0] + rrow*80 + rc)      = pa0;
            *(uint4*)((char*)&sA[nb][0] + (rrow+64)*80 + rc) = pa1;
            *(uint4*)((char*)&sB[nb][0] + rrow*80 + rc)      = pb0;
            *(uint4*)((char*)&sB[nb][0] + (rrow+64)*80 + rc) = pb1;
        }
        __syncthreads();
    }

    const int b = bh >> 4;
    const int r0 = m0 + wm*32 + (lane >> 2);
    const int cb = wn*64 + ((lane & 3) << 1);
    #pragma unroll
    for (int mi = 0; mi < 2; mi++)
        #pragma unroll
        for (int nj = 0; nj < 8; nj++) {
            const int n = n0 + cb + nj*8;
            const float mkx = (1.0f - mask[b*SEQ + n])   * -1e9f;
            const float mky = (1.0f - mask[b*SEQ + n+1]) * -1e9f;
            const int row = r0 + mi*16;
            float2 v0 = make_float2(acc[mi][nj][0]*0.125f + mkx,
                                    acc[mi][nj][1]*0.125f + mky);
            float2 v1 = make_float2(acc[mi][nj][2]*0.125f + mkx,
                                    acc[mi][nj][3]*0.125f + mky);
            *(float2*)(g_S + ((size_t)bh*SEQ + row)*SEQ + n)     = v0;
            *(float2*)(g_S + ((size_t)bh*SEQ + row + 8)*SEQ + n) = v1;
        }
}

// ---------------------------------------------------------------------------
// softmax: row softmax of g_S -> bf16 hi/lo P buffers
// ---------------------------------------------------------------------------
__global__ void __launch_bounds__(256) softmax_kernel()
{
    const size_t roff = (size_t)blockIdx.x * SEQ;
    const float* p = g_S + roff;
    const int t = threadIdx.x;
    float v[8];
    float mx = -1e30f;
    #pragma unroll
    for (int i = 0; i < 8; i++) { v[i] = p[t + (i << 8)]; mx = fmaxf(mx, v[i]); }
    #pragma unroll
    for (int o = 16; o > 0; o >>= 1) mx = fmaxf(mx, __shfl_xor_sync(0xffffffffu, mx, o));
    __shared__ float redm[8];
    __shared__ float reds[8];
    if ((t & 31) == 0) redm[t >> 5] = mx;
    __syncthreads();
    mx = redm[0];
    #pragma unroll
    for (int i = 1; i < 8; i++) mx = fmaxf(mx, redm[i]);

    float sum = 0.f;
    #pragma unroll
    for (int i = 0; i < 8; i++) { v[i] = __expf(v[i] - mx); sum += v[i]; }
    #pragma unroll
    for (int o = 16; o > 0; o >>= 1) sum += __shfl_xor_sync(0xffffffffu, sum, o);
    if ((t & 31) == 0) reds[t >> 5] = sum;
    __syncthreads();
    sum = 0.f;
    #pragma unroll
    for (int i = 0; i < 8; i++) sum += reds[i];
    const float inv = 1.0f / sum;
    #pragma unroll
    for (int i = 0; i < 8; i++) {
        float pv = v[i] * inv;
        __nv_bfloat16 hi = __float2bfloat16(pv);
        float lo = pv - __bfloat162float(hi);
        g_Phi[roff + t + (i << 8)] = __bfloat16_as_ushort(hi);
        g_Plo[roff + t + (i << 8)] = __bfloat16_as_ushort(__float2bfloat16(lo));
    }
}

// ---------------------------------------------------------------------------
// pv_mma: out = Phi.Vhi + Phi.Vlo + Plo.Vhi  (M=128 tile, N=128, K=2048 x3)
// Writes o-proj input g_Xhi/g_Xlo directly: col = comp*1024 + h*64 + d.
// ---------------------------------------------------------------------------
__global__ void __launch_bounds__(256, 2) pv_mma()
{
    __shared__ __align__(16) __nv_bfloat16 sA[2][128*40];
    __shared__ __align__(16) __nv_bfloat16 sB[2][128*40];

    const int t    = threadIdx.x;
    const int lane = t & 31;
    const int wid  = t >> 5;
    const int wm   = wid & 3;
    const int wn   = wid >> 2;
    const int bh   = blockIdx.z;
    const int m0   = blockIdx.y << 7;

    const char* Phi = (const char*)(g_Phi + ((size_t)bh*SEQ + m0)*SEQ);
    const char* Plo = (const char*)(g_Plo + ((size_t)bh*SEQ + m0)*SEQ);
    const char* Vhi = (const char*)(g_VThi + (size_t)bh*128*SEQ);
    const char* Vlo = (const char*)(g_VTlo + (size_t)bh*128*SEQ);

    float acc[2][8][4];
    #pragma unroll
    for (int i = 0; i < 2; i++)
        #pragma unroll
        for (int j = 0; j < 8; j++)
            #pragma unroll
            for (int q = 0; q < 4; q++) acc[i][j][q] = 0.f;

    const unsigned sAb = smem_u32(&sA[0][0]);
    const unsigned sBb = smem_u32(&sB[0][0]);
    const int rrow = t >> 2, rc = (t & 3) << 4;

    {
        uint4 a0 = *(const uint4*)(Phi + (size_t)rrow*(SEQ*2) + rc);
        uint4 a1 = *(const uint4*)(Phi + (size_t)(rrow+64)*(SEQ*2) + rc);
        uint4 b0 = *(const uint4*)(Vhi + (size_t)rrow*(SEQ*2) + rc);
        uint4 b1 = *(const uint4*)(Vhi + (size_t)(rrow+64)*(SEQ*2) + rc);
        *(uint4*)((char*)&sA[0][0] + rrow*80 + rc)      = a0;
        *(uint4*)((char*)&sA[0][0] + (rrow+64)*80 + rc) = a1;
        *(uint4*)((char*)&sB[0][0] + rrow*80 + rc)      = b0;
        *(uint4*)((char*)&sB[0][0] + (rrow+64)*80 + rc) = b1;
    }
    __syncthreads();

    for (int cc = 0; cc < 192; cc++) {
        const int buf = cc & 1;
        uint4 pa0, pa1, pb0, pb1;
        const bool pf = (cc + 1 < 192);
        if (pf) {
            const int nc = cc + 1, pass = nc >> 6, kt = (nc & 63) << 5;
            const char* Ap = (pass == 2 ? Plo : Phi) + kt*2;
            const char* Bp = (pass == 1 ? Vlo : Vhi) + kt*2;
            pa0 = *(const uint4*)(Ap + (size_t)rrow*(SEQ*2) + rc);
            pa1 = *(const uint4*)(Ap + (size_t)(rrow+64)*(SEQ*2) + rc);
            pb0 = *(const uint4*)(Bp + (size_t)rrow*(SEQ*2) + rc);
            pb1 = *(const uint4*)(Bp + (size_t)(rrow+64)*(SEQ*2) + rc);
        }
        gemm_chunk(sAb + buf*10240, sBb + buf*10240, wm, wn, lane, acc);
        if (pf) {
            const int nb = buf ^ 1;
            *(uint4*)((char*)&sA[nb][0] + rrow*80 + rc)      = pa0;
            *(uint4*)((char*)&sA[nb][0] + (rrow+64)*80 + rc) = pa1;
            *(uint4*)((char*)&sB[nb][0] + rrow*80 + rc)      = pb0;
            *(uint4*)((char*)&sB[nb][0] + (rrow+64)*80 + rc) = pb1;
        }
        __syncthreads();
    }

    const int b = bh >> 4, h = bh & 15;
    const int r0 = m0 + wm*32 + (lane >> 2);
    const int cb = wn*64 + ((lane & 3) << 1);
    #pragma unroll
    for (int mi = 0; mi < 2; mi++)
        #pragma unroll
        for (int nj = 0; nj < 8; nj++) {
            const int n = cb + nj*8;                 // 0..127
            const int comp = n >> 6, d = n & 63;
            const int col = comp*1024 + h*64 + d;
            const int row = r0 + mi*16;
            #pragma unroll
            for (int rr = 0; rr < 2; rr++) {
                const float x = acc[mi][nj][rr*2 + 0];
                const float y = acc[mi][nj][rr*2 + 1];
                unsigned hi, lo; split2(x, y, hi, lo);
                size_t base = (size_t)(b*SEQ + row + rr*8)*GK + col;
                *(unsigned*)(g_Xhi + base) = hi;
                *(unsigned*)(g_Xlo + base) = lo;
            }
        }
}

// ---------------------------------------------------------------------------
extern "C" void kernel_launch(void* const* d_in, const int* in_sizes, int n_in,
                              void* d_out, int out_size)
{
    (void)in_sizes; (void)n_in; (void)out_size;
    const float* x_r  = (const float*)d_in[0];
    const float* x_i  = (const float*)d_in[1];
    const float* mask = (const float*)d_in[2];
    const float* Wq_r = (const float*)d_in[3];
    const float* Wq_i = (const float*)d_in[4];
    const float* bq_r = (const float*)d_in[5];
    const float* bq_i = (const float*)d_in[6];
    const float* Wk_r = (const float*)d_in[7];
    const float* Wk_i = (const float*)d_in[8];
    const float* bk_r = (const float*)d_in[9];
    const float* bk_i = (const float*)d_in[10];
    const float* Wv_r = (const float*)d_in[11];
    const float* Wv_i = (const float*)d_in[12];
    const float* bv_r = (const float*)d_in[13];
    const float* bv_i = (const float*)d_in[14];
    const float* Wo_r = (const float*)d_in[15];
    const float* Wo_i = (const float*)d_in[16];
    const float* bo_r = (const float*)d_in[17];
    const float* bo_i = (const float*)d_in[18];
    float* out = (float*)d_out;

    pack_x<<<MTOT*GK/256, 256>>>(x_r, x_i);
    pack_w<<<dim3(64, 64), 256>>>(Wq_r, Wq_i, 0);
    pack_w<<<dim3(64, 64), 256>>>(Wk_r, Wk_i, 2048);
    pack_w<<<dim3(64, 64), 256>>>(Wv_r, Wv_i, 4096);
    pack_w<<<dim3(64, 64), 256>>>(Wo_r, Wo_i, 6144);
    pack_bias<<<8, 256>>>(bq_r, bq_i, 0);
    pack_bias<<<8, 256>>>(bk_r, bk_i, 2048);
    pack_bias<<<8, 256>>>(bv_r, bv_i, 4096);
    pack_bias<<<8, 256>>>(bo_r, bo_i, 6144);

    // QKV projection (HMMA) -> packed Q/K bf16 (384-dim), V fp32
    tgemm<0><<<dim3(48, 32), 256>>>(nullptr, 0);
    pack_vt<<<dim3(SEQ/32, 4, BHT), 256>>>();

    // attention on HMMA
    scores_mma<<<dim3(SEQ/128, SEQ/128, BHT), 256>>>(mask);
    softmax_kernel<<<BHT*SEQ, 256>>>();
    pv_mma<<<dim3(1, SEQ/128, BHT), 256>>>();

    // output projection (HMMA) -> d_out
    tgemm<1><<<dim3(16, 32), 256>>>(out, 6144);
}

// round 15
// speedup vs baseline: 1.2512x; 1.2470x over previous
#include <cuda_runtime.h>
#include <cuda_bf16.h>

#define BATCH 2
#define SEQ   2048
#define FEAT  1024
#define NH    16
#define HD    64
#define MTOT  (BATCH*SEQ)     // 4096
#define BHT   (BATCH*NH)      // 32
#define GK    2048            // complex-concat K dim

// ---------------- scratch (static device globals; no allocation) ----------
__device__ unsigned short g_Xhi[MTOT*GK];            // bf16 hi of [xr|xi] / attn out
__device__ unsigned short g_Xlo[MTOT*GK];            // bf16 lo
__device__ unsigned short g_Whi[8192*GK];            // W^T K-major: QKV 0..6143, O 6144..8191
__device__ unsigned short g_Wlo[8192*GK];
__device__ float g_bias[8192];

__device__ unsigned short g_Qhi[(size_t)BHT*SEQ*128];  // [bh][s][r|i]
__device__ unsigned short g_Qlo[(size_t)BHT*SEQ*128];
__device__ unsigned short g_Khi[(size_t)BHT*SEQ*128];
__device__ unsigned short g_Klo[(size_t)BHT*SEQ*128];
__device__ float          g_V [(size_t)BHT*SEQ*128];   // [bh][s][r(64)|i(64)] fp32
__device__ unsigned short g_VThi[(size_t)BHT*128*SEQ]; // [bh][d(r|i)][s]
__device__ unsigned short g_VTlo[(size_t)BHT*128*SEQ];
__device__ float          g_S  [(size_t)BHT*SEQ*SEQ];  // scores fp32, 512 MB
__device__ unsigned short g_Phi[(size_t)BHT*SEQ*SEQ];  // softmax hi, 256 MB
__device__ unsigned short g_Plo[(size_t)BHT*SEQ*SEQ];  // softmax lo, 256 MB

// ---------------------------- helpers --------------------------------------
__device__ __forceinline__ unsigned smem_u32(const void* p) {
    unsigned a;
    asm("{ .reg .u64 t; cvta.to.shared.u64 t, %1; cvt.u32.u64 %0, t; }"
        : "=r"(a) : "l"(p));
    return a;
}
__device__ __forceinline__ void ldm_x4(unsigned* r, unsigned addr) {
    asm volatile("ldmatrix.sync.aligned.m8n8.x4.shared.b16 {%0,%1,%2,%3}, [%4];"
                 : "=r"(r[0]), "=r"(r[1]), "=r"(r[2]), "=r"(r[3]) : "r"(addr));
}
__device__ __forceinline__ void mma_bf16(float* c, const unsigned* a,
                                         unsigned b0, unsigned b1) {
    asm volatile(
        "mma.sync.aligned.m16n8k16.row.col.f32.bf16.bf16.f32 "
        "{%0,%1,%2,%3}, {%4,%5,%6,%7}, {%8,%9}, {%0,%1,%2,%3};"
        : "+f"(c[0]), "+f"(c[1]), "+f"(c[2]), "+f"(c[3])
        : "r"(a[0]), "r"(a[1]), "r"(a[2]), "r"(a[3]), "r"(b0), "r"(b1));
}
__device__ __forceinline__ void split2(float x, float y, unsigned& hi, unsigned& lo) {
    __nv_bfloat16 hx = __float2bfloat16(x), hy = __float2bfloat16(y);
    float rx = x - __bfloat162float(hx), ry = y - __bfloat162float(hy);
    __nv_bfloat16 lx = __float2bfloat16(rx), ly = __float2bfloat16(ry);
    hi = ((unsigned)__bfloat16_as_ushort(hy) << 16) | __bfloat16_as_ushort(hx);
    lo = ((unsigned)__bfloat16_as_ushort(ly) << 16) | __bfloat16_as_ushort(lx);
}
__device__ __forceinline__ void cp16(unsigned sdst, const void* gsrc) {
    asm volatile("cp.async.cg.shared.global [%0], [%1], 16;"
                 :: "r"(sdst), "l"(__cvta_generic_to_global(gsrc)));
}
// stage one 128-row x 64B (k32) tile slice into SMEM (stride 80B, 2 rows/thread)
__device__ __forceinline__ void tile_load(unsigned sdst, const char* src,
                                          size_t stride, int rrow, int rc) {
    cp16(sdst + rrow*80 + rc,      src + (size_t)rrow*stride + rc);
    cp16(sdst + (rrow+64)*80 + rc, src + (size_t)(rrow+64)*stride + rc);
}
// fused k32 chunk: acc += Ahi.Bhi + Alo.Bhi + Ahi.Blo   (128x128 warp-tiled)
__device__ __forceinline__ void fused_chunk(unsigned sAh, unsigned sAl,
                                            unsigned sBh, unsigned sBl,
                                            int wm, int wn, int lane,
                                            float acc[2][8][4]) {
    const int mtx = lane >> 3, rowi = lane & 7;
    #pragma unroll
    for (int s = 0; s < 2; s++) {
        const unsigned aoff = (wm*32 + (lane & 15))*80 + ((lane >> 4)*8 + s*16)*2;
        unsigned ah[2][4], al[2][4];
        ldm_x4(ah[0], sAh + aoff);
        ldm_x4(ah[1], sAh + aoff + 16*80);
        ldm_x4(al[0], sAl + aoff);
        ldm_x4(al[1], sAl + aoff + 16*80);
        const unsigned boff = (wn*64 + ((mtx >> 1) << 3) + rowi)*80
                            + (s*16 + ((mtx & 1) << 3))*2;
        {   // B = hi: hi.hi and lo.hi
            unsigned b_[8][2];
            #pragma unroll
            for (int np = 0; np < 4; np++) {
                unsigned r[4];
                ldm_x4(r, sBh + boff + np*16*80);
                b_[np*2+0][0]=r[0]; b_[np*2+0][1]=r[1];
                b_[np*2+1][0]=r[2]; b_[np*2+1][1]=r[3];
            }
            #pragma unroll
            for (int mi = 0; mi < 2; mi++)
                #pragma unroll
                for (int nj = 0; nj < 8; nj++)
                    mma_bf16(acc[mi][nj], ah[mi], b_[nj][0], b_[nj][1]);
            #pragma unroll
            for (int mi = 0; mi < 2; mi++)
                #pragma unroll
                for (int nj = 0; nj < 8; nj++)
                    mma_bf16(acc[mi][nj], al[mi], b_[nj][0], b_[nj][1]);
        }
        {   // B = lo: hi.lo
            unsigned b_[8][2];
            #pragma unroll
            for (int np = 0; np < 4; np++) {
                unsigned r[4];
                ldm_x4(r, sBl + boff + np*16*80);
                b_[np*2+0][0]=r[0]; b_[np*2+0][1]=r[1];
                b_[np*2+1][0]=r[2]; b_[np*2+1][1]=r[3];
            }
            #pragma unroll
            for (int mi = 0; mi < 2; mi++)
                #pragma unroll
                for (int nj = 0; nj < 8; nj++)
                    mma_bf16(acc[mi][nj], ah[mi], b_[nj][0], b_[nj][1]);
        }
    }
}
#define SMEM_FUSED 81920   // 2 buffers x 4 tiles x 10240 B

// ---------------------------------------------------------------------------
// pack kernels (unchanged)
// ---------------------------------------------------------------------------
__global__ void pack_x(const float* __restrict__ xr, const float* __restrict__ xi)
{
    int idx = blockIdx.x * 256 + threadIdx.x;
    int m = idx >> 11, n = idx & 2047;
    float v = (n < 1024) ? xr[(size_t)m*1024 + n] : xi[(size_t)m*1024 + n - 1024];
    __nv_bfloat16 hi = __float2bfloat16(v);
    float lo = v - __bfloat162float(hi);
    g_Xhi[idx] = __bfloat16_as_ushort(hi);
    g_Xlo[idx] = __bfloat16_as_ushort(__float2bfloat16(lo));
}

__global__ void pack_w(const float* __restrict__ Wr, const float* __restrict__ Wi,
                       int n_offset)
{
    __shared__ float s[32*33];
    const int t = threadIdx.x;
    const int nl0 = blockIdx.x << 5;
    const int k0  = blockIdx.y << 5;
    const int comp = nl0 >> 10;
    const int j0 = nl0 & 1023;

    const float* src; float sgn = 1.0f; int kr0;
    if (k0 < 1024) { kr0 = k0; src = comp ? Wi : Wr; }
    else { kr0 = k0 - 1024; if (comp) src = Wr; else { src = Wi; sgn = -1.0f; } }

    #pragma unroll
    for (int p = 0; p < 4; p++) {
        int e = p*256 + t, kr = e >> 5, jc = e & 31;
        s[kr*33 + jc] = src[(size_t)(kr0 + kr)*1024 + j0 + jc] * sgn;
    }
    __syncthreads();
    #pragma unroll
    for (int p = 0; p < 4; p++) {
        int e = p*256 + t, nr = e >> 5, kc = e & 31;
        float v = s[kc*33 + nr];
        __nv_bfloat16 hi = __float2bfloat16(v);
        float lo = v - __bfloat162float(hi);
        size_t o = (size_t)(n_offset + nl0 + nr)*GK + k0 + kc;
        g_Whi[o] = __bfloat16_as_ushort(hi);
        g_Wlo[o] = __bfloat16_as_ushort(__float2bfloat16(lo));
    }
}

__global__ void pack_bias(const float* __restrict__ br, const float* __restrict__ bi,
                          int off)
{
    int n = blockIdx.x * 256 + threadIdx.x;
    g_bias[off + n] = (n < 1024) ? br[n] : bi[n - 1024];
}

// ---------------------------------------------------------------------------
// tgemm: fused split-bf16 HMMA GEMM over K=2048 (one sweep, 3 terms per chunk)
// MODE 0 (QKV): Q -> g_Qhi/lo, K -> g_Khi/lo (128-dim head layout), V fp32.
// MODE 1 (O):   write fp32 to Cout split by comp.
// ---------------------------------------------------------------------------
template<int MODE>
__global__ void __launch_bounds__(256, 2) tgemm(float* __restrict__ Cout, int nb_off)
{
    extern __shared__ char dsm[];
    const unsigned sb = smem_u32(dsm);

    const int t    = threadIdx.x;
    const int lane = t & 31;
    const int wid  = t >> 5;
    const int wm   = wid & 3;
    const int wn   = wid >> 2;
    const int m0   = blockIdx.y << 7;
    const int n0   = blockIdx.x << 7;
    const int rrow = t >> 2, rc = (t & 3) << 4;

    const char* Ah = (const char*)g_Xhi + (size_t)m0*(GK*2);
    const char* Al = (const char*)g_Xlo + (size_t)m0*(GK*2);
    const char* Bh = (const char*)(g_Whi + (size_t)nb_off*GK) + (size_t)n0*(GK*2);
    const char* Bl = (const char*)(g_Wlo + (size_t)nb_off*GK) + (size_t)n0*(GK*2);

    float acc[2][8][4];
    #pragma unroll
    for (int i = 0; i < 2; i++)
        #pragma unroll
        for (int j = 0; j < 8; j++)
            #pragma unroll
            for (int q = 0; q < 4; q++) acc[i][j][q] = 0.f;

    auto issue = [&](int cc, int buf) {
        const unsigned base = sb + buf*40960;
        const size_t ko = (size_t)cc*64;
        tile_load(base,         Ah + ko, GK*2, rrow, rc);
        tile_load(base+10240,   Al + ko, GK*2, rrow, rc);
        tile_load(base+20480,   Bh + ko, GK*2, rrow, rc);
        tile_load(base+30720,   Bl + ko, GK*2, rrow, rc);
        asm volatile("cp.async.commit_group;" ::: "memory");
    };

    issue(0, 0);
    for (int cc = 0; cc < 64; cc++) {
        const int buf = cc & 1;
        const bool pf = (cc + 1 < 64);
        if (pf) issue(cc + 1, buf ^ 1);
        if (pf) asm volatile("cp.async.wait_group 1;" ::: "memory");
        else    asm volatile("cp.async.wait_group 0;" ::: "memory");
        __syncthreads();
        const unsigned base = sb + buf*40960;
        fused_chunk(base, base+10240, base+20480, base+30720, wm, wn, lane, acc);
        __syncthreads();
    }

    const int r0 = m0 + wm*32 + (lane >> 2);
    const int cb = wn*64 + ((lane & 3) << 1);
    #pragma unroll
    for (int mi = 0; mi < 2; mi++)
        #pragma unroll
        for (int nj = 0; nj < 8; nj++) {
            const int n = n0 + cb + nj*8;
            const float bx = g_bias[nb_off + n];
            const float by = g_bias[nb_off + n + 1];
            float2 v0 = make_float2(acc[mi][nj][0] + bx, acc[mi][nj][1] + by);
            float2 v1 = make_float2(acc[mi][nj][2] + bx, acc[mi][nj][3] + by);
            const int row = r0 + mi*16;
            if (MODE == 0) {
                const int proj = n >> 11, rem = n & 2047;
                const int comp = rem >> 10, j = rem & 1023;
                const int h = j >> 6, d = j & 63;
                #pragma unroll
                for (int rr = 0; rr < 2; rr++) {
                    const int rw = row + rr*8;
                    const float2 v = rr ? v1 : v0;
                    const int bh = (rw >> 11)*NH + h, sq = rw & 2047;
                    if (proj == 0) {
                        unsigned hi, lo; split2(v.x, v.y, hi, lo);
                        size_t base = ((size_t)bh*SEQ + sq)*128 + comp*64 + d;
                        *(unsigned*)(g_Qhi + base) = hi;
                        *(unsigned*)(g_Qlo + base) = lo;
                    } else if (proj == 1) {
                        unsigned hi, lo; split2(v.x, v.y, hi, lo);
                        size_t base = ((size_t)bh*SEQ + sq)*128 + comp*64 + d;
                        *(unsigned*)(g_Khi + base) = hi;
                        *(unsigned*)(g_Klo + base) = lo;
                    } else {
                        *(float2*)(g_V + ((size_t)bh*SEQ + sq)*128 + comp*64 + d) = v;
                    }
                }
            } else {
                const int comp = n >> 10, j = n & 1023;
                float* dst = Cout + (size_t)comp*((size_t)MTOT*FEAT) + j;
                *(float2*)(dst + (size_t)row*FEAT)     = v0;
                *(float2*)(dst + (size_t)(row+8)*FEAT) = v1;
            }
        }
}

// ---------------------------------------------------------------------------
// pack_vt: g_V [bh][s][128] fp32 -> transposed bf16 hi/lo [bh][d128][s]
// ---------------------------------------------------------------------------
__global__ void pack_vt()
{
    __shared__ float sm[32*33];
    const int t = threadIdx.x;
    const int bh = blockIdx.z;
    const int c0 = blockIdx.y << 5;
    const int s0 = blockIdx.x << 5;

    #pragma unroll
    for (int p = 0; p < 4; p++) {
        int e = p*256 + t, r = e >> 5, c = e & 31;
        sm[r*33 + c] = g_V[((size_t)bh*SEQ + s0 + r)*128 + c0 + c];
    }
    __syncthreads();
    #pragma unroll
    for (int p = 0; p < 4; p++) {
        int e = p*256 + t, r = e >> 5, c = e & 31;
        float v = sm[c*33 + r];
        __nv_bfloat16 hi = __float2bfloat16(v);
        float lo = v - __bfloat162float(hi);
        size_t o = ((size_t)bh*128 + c0 + r)*SEQ + s0 + c;
        g_VThi[o] = __bfloat16_as_ushort(hi);
        g_VTlo[o] = __bfloat16_as_ushort(__float2bfloat16(lo));
    }
}

// ---------------------------------------------------------------------------
// scores_mma: S = 0.125*(Qhi.Khi + Qlo.Khi + Qhi.Klo) + mask   (K=128, fused)
// ---------------------------------------------------------------------------
__global__ void __launch_bounds__(256, 2) scores_mma(const float* __restrict__ mask)
{
    extern __shared__ char dsm[];
    const unsigned sb = smem_u32(dsm);

    const int t    = threadIdx.x;
    const int lane = t & 31;
    const int wid  = t >> 5;
    const int wm   = wid & 3;
    const int wn   = wid >> 2;
    const int bh   = blockIdx.z;
    const int m0   = blockIdx.y << 7;
    const int n0   = blockIdx.x << 7;
    const int rrow = t >> 2, rc = (t & 3) << 4;

    const char* Ah = (const char*)(g_Qhi + ((size_t)bh*SEQ + m0)*128);
    const char* Al = (const char*)(g_Qlo + ((size_t)bh*SEQ + m0)*128);
    const char* Bh = (const char*)(g_Khi + ((size_t)bh*SEQ + n0)*128);
    const char* Bl = (const char*)(g_Klo + ((size_t)bh*SEQ + n0)*128);

    float acc[2][8][4];
    #pragma unroll
    for (int i = 0; i < 2; i++)
        #pragma unroll
        for (int j = 0; j < 8; j++)
            #pragma unroll
            for (int q = 0; q < 4; q++) acc[i][j][q] = 0.f;

    auto issue = [&](int cc, int buf) {
        const unsigned base = sb + buf*40960;
        const size_t ko = (size_t)cc*64;
        tile_load(base,         Ah + ko, 256, rrow, rc);
        tile_load(base+10240,   Al + ko, 256, rrow, rc);
        tile_load(base+20480,   Bh + ko, 256, rrow, rc);
        tile_load(base+30720,   Bl + ko, 256, rrow, rc);
        asm volatile("cp.async.commit_group;" ::: "memory");
    };

    issue(0, 0);
    for (int cc = 0; cc < 4; cc++) {
        const int buf = cc & 1;
        const bool pf = (cc + 1 < 4);
        if (pf) issue(cc + 1, buf ^ 1);
        if (pf) asm volatile("cp.async.wait_group 1;" ::: "memory");
        else    asm volatile("cp.async.wait_group 0;" ::: "memory");
        __syncthreads();
        const unsigned base = sb + buf*40960;
        fused_chunk(base, base+10240, base+20480, base+30720, wm, wn, lane, acc);
        __syncthreads();
    }

    const int b = bh >> 4;
    const int r0 = m0 + wm*32 + (lane >> 2);
    const int cb = wn*64 + ((lane & 3) << 1);
    #pragma unroll
    for (int mi = 0; mi < 2; mi++)
        #pragma unroll
        for (int nj = 0; nj < 8; nj++) {
            const int n = n0 + cb + nj*8;
            const float mkx = (1.0f - mask[b*SEQ + n])   * -1e9f;
            const float mky = (1.0f - mask[b*SEQ + n+1]) * -1e9f;
            const int row = r0 + mi*16;
            float2 v0 = make_float2(acc[mi][nj][0]*0.125f + mkx,
                                    acc[mi][nj][1]*0.125f + mky);
            float2 v1 = make_float2(acc[mi][nj][2]*0.125f + mkx,
                                    acc[mi][nj][3]*0.125f + mky);
            *(float2*)(g_S + ((size_t)bh*SEQ + row)*SEQ + n)     = v0;
            *(float2*)(g_S + ((size_t)bh*SEQ + row + 8)*SEQ + n) = v1;
        }
}

// ---------------------------------------------------------------------------
// softmax: row softmax of g_S -> bf16 hi/lo P buffers (unchanged)
// ---------------------------------------------------------------------------
__global__ void __launch_bounds__(256) softmax_kernel()
{
    const size_t roff = (size_t)blockIdx.x * SEQ;
    const float* p = g_S + roff;
    const int t = threadIdx.x;
    float v[8];
    float mx = -1e30f;
    #pragma unroll
    for (int i = 0; i < 8; i++) { v[i] = p[t + (i << 8)]; mx = fmaxf(mx, v[i]); }
    #pragma unroll
    for (int o = 16; o > 0; o >>= 1) mx = fmaxf(mx, __shfl_xor_sync(0xffffffffu, mx, o));
    __shared__ float redm[8];
    __shared__ float reds[8];
    if ((t & 31) == 0) redm[t >> 5] = mx;
    __syncthreads();
    mx = redm[0];
    #pragma unroll
    for (int i = 1; i < 8; i++) mx = fmaxf(mx, redm[i]);

    float sum = 0.f;
    #pragma unroll
    for (int i = 0; i < 8; i++) { v[i] = __expf(v[i] - mx); sum += v[i]; }
    #pragma unroll
    for (int o = 16; o > 0; o >>= 1) sum += __shfl_xor_sync(0xffffffffu, sum, o);
    if ((t & 31) == 0) reds[t >> 5] = sum;
    __syncthreads();
    sum = 0.f;
    #pragma unroll
    for (int i = 0; i < 8; i++) sum += reds[i];
    const float inv = 1.0f / sum;
    #pragma unroll
    for (int i = 0; i < 8; i++) {
        float pv = v[i] * inv;
        __nv_bfloat16 hi = __float2bfloat16(pv);
        float lo = pv - __bfloat162float(hi);
        g_Phi[roff + t + (i << 8)] = __bfloat16_as_ushort(hi);
        g_Plo[roff + t + (i << 8)] = __bfloat16_as_ushort(__float2bfloat16(lo));
    }
}

// ---------------------------------------------------------------------------
// pv_mma: out = Phi.Vhi + Plo.Vhi + Phi.Vlo  (K=2048, fused single sweep)
// Writes o-proj input g_Xhi/g_Xlo directly: col = comp*1024 + h*64 + d.
// ---------------------------------------------------------------------------
__global__ void __launch_bounds__(256, 2) pv_mma()
{
    extern __shared__ char dsm[];
    const unsigned sb = smem_u32(dsm);

    const int t    = threadIdx.x;
    const int lane = t & 31;
    const int wid  = t >> 5;
    const int wm   = wid & 3;
    const int wn   = wid >> 2;
    const int bh   = blockIdx.z;
    const int m0   = blockIdx.y << 7;
    const int rrow = t >> 2, rc = (t & 3) << 4;

    const char* Ah = (const char*)(g_Phi + ((size_t)bh*SEQ + m0)*SEQ);
    const char* Al = (const char*)(g_Plo + ((size_t)bh*SEQ + m0)*SEQ);
    const char* Bh = (const char*)(g_VThi + (size_t)bh*128*SEQ);
    const char* Bl = (const char*)(g_VTlo + (size_t)bh*128*SEQ);

    float acc[2][8][4];
    #pragma unroll
    for (int i = 0; i < 2; i++)
        #pragma unroll
        for (int j = 0; j < 8; j++)
            #pragma unroll
            for (int q = 0; q < 4; q++) acc[i][j][q] = 0.f;

    auto issue = [&](int cc, int buf) {
        const unsigned base = sb + buf*40960;
        const size_t ko = (size_t)cc*64;
        tile_load(base,         Ah + ko, SEQ*2, rrow, rc);
        tile_load(base+10240,   Al + ko, SEQ*2, rrow, rc);
        tile_load(base+20480,   Bh + ko, SEQ*2, rrow, rc);
        tile_load(base+30720,   Bl + ko, SEQ*2, rrow, rc);
        asm volatile("cp.async.commit_group;" ::: "memory");
    };

    issue(0, 0);
    for (int cc = 0; cc < 64; cc++) {
        const int buf = cc & 1;
        const bool pf = (cc + 1 < 64);
        if (pf) issue(cc + 1, buf ^ 1);
        if (pf) asm volatile("cp.async.wait_group 1;" ::: "memory");
        else    asm volatile("cp.async.wait_group 0;" ::: "memory");
        __syncthreads();
        const unsigned base = sb + buf*40960;
        fused_chunk(base, base+10240, base+20480, base+30720, wm, wn, lane, acc);
        __syncthreads();
    }

    const int b = bh >> 4, h = bh & 15;
    const int r0 = m0 + wm*32 + (lane >> 2);
    const int cb = wn*64 + ((lane & 3) << 1);
    #pragma unroll
    for (int mi = 0; mi < 2; mi++)
        #pragma unroll
        for (int nj = 0; nj < 8; nj++) {
            const int n = cb + nj*8;
            const int comp = n >> 6, d = n & 63;
            const int col = comp*1024 + h*64 + d;
            const int row = r0 + mi*16;
            #pragma unroll
            for (int rr = 0; rr < 2; rr++) {
                const float x = acc[mi][nj][rr*2 + 0];
                const float y = acc[mi][nj][rr*2 + 1];
                unsigned hi, lo; split2(x, y, hi, lo);
                size_t base = (size_t)(b*SEQ + row + rr*8)*GK + col;
                *(unsigned*)(g_Xhi + base) = hi;
                *(unsigned*)(g_Xlo + base) = lo;
            }
        }
}

// ---------------------------------------------------------------------------
extern "C" void kernel_launch(void* const* d_in, const int* in_sizes, int n_in,
                              void* d_out, int out_size)
{
    (void)in_sizes; (void)n_in; (void)out_size;
    const float* x_r  = (const float*)d_in[0];
    const float* x_i  = (const float*)d_in[1];
    const float* mask = (const float*)d_in[2];
    const float* Wq_r = (const float*)d_in[3];
    const float* Wq_i = (const float*)d_in[4];
    const float* bq_r = (const float*)d_in[5];
    const float* bq_i = (const float*)d_in[6];
    const float* Wk_r = (const float*)d_in[7];
    const float* Wk_i = (const float*)d_in[8];
    const float* bk_r = (const float*)d_in[9];
    const float* bk_i = (const float*)d_in[10];
    const float* Wv_r = (const float*)d_in[11];
    const float* Wv_i = (const float*)d_in[12];
    const float* bv_r = (const float*)d_in[13];
    const float* bv_i = (const float*)d_in[14];
    const float* Wo_r = (const float*)d_in[15];
    const float* Wo_i = (const float*)d_in[16];
    const float* bo_r = (const float*)d_in[17];
    const float* bo_i = (const float*)d_in[18];
    float* out = (float*)d_out;

    cudaFuncSetAttribute(tgemm<0>, cudaFuncAttributeMaxDynamicSharedMemorySize, SMEM_FUSED);
    cudaFuncSetAttribute(tgemm<1>, cudaFuncAttributeMaxDynamicSharedMemorySize, SMEM_FUSED);
    cudaFuncSetAttribute(scores_mma, cudaFuncAttributeMaxDynamicSharedMemorySize, SMEM_FUSED);
    cudaFuncSetAttribute(pv_mma, cudaFuncAttributeMaxDynamicSharedMemorySize, SMEM_FUSED);

    pack_x<<<MTOT*GK/256, 256>>>(x_r, x_i);
    pack_w<<<dim3(64, 64), 256>>>(Wq_r, Wq_i, 0);
    pack_w<<<dim3(64, 64), 256>>>(Wk_r, Wk_i, 2048);
    pack_w<<<dim3(64, 64), 256>>>(Wv_r, Wv_i, 4096);
    pack_w<<<dim3(64, 64), 256>>>(Wo_r, Wo_i, 6144);
    pack_bias<<<8, 256>>>(bq_r, bq_i, 0);
    pack_bias<<<8, 256>>>(bk_r, bk_i, 2048);
    pack_bias<<<8, 256>>>(bv_r, bv_i, 4096);
    pack_bias<<<8, 256>>>(bo_r, bo_i, 6144);

    // QKV projection (fused HMMA) -> Q/K hi/lo (128-dim), V fp32
    tgemm<0><<<dim3(48, 32), 256, SMEM_FUSED>>>(nullptr, 0);
    pack_vt<<<dim3(SEQ/32, 4, BHT), 256>>>();

    // attention on HMMA (fused split precision)
    scores_mma<<<dim3(SEQ/128, SEQ/128, BHT), 256, SMEM_FUSED>>>(mask);
    softmax_kernel<<<BHT*SEQ, 256>>>();
    pv_mma<<<dim3(1, SEQ/128, BHT), 256, SMEM_FUSED>>>();

    // output projection (fused HMMA) -> d_out
    tgemm<1><<<dim3(16, 32), 256, SMEM_FUSED>>>(out, 6144);
}

// round 16
// speedup vs baseline: 1.2524x; 1.0010x over previous
#include <cuda_runtime.h>
#include <cuda_bf16.h>

#define BATCH 2
#define SEQ   2048
#define FEAT  1024
#define NH    16
#define HD    64
#define MTOT  (BATCH*SEQ)     // 4096
#define BHT   (BATCH*NH)      // 32
#define GK    2048            // complex-concat K dim

// ---------------- scratch (static device globals; no allocation) ----------
__device__ unsigned short g_Xhi[MTOT*GK];            // bf16 hi of [xr|xi] / attn out
__device__ unsigned short g_Xlo[MTOT*GK];            // bf16 lo
__device__ unsigned short g_Whi[8192*GK];            // W^T K-major: QKV 0..6143, O 6144..8191
__device__ unsigned short g_Wlo[8192*GK];
__device__ float g_bias[8192];

__device__ unsigned short g_Qhi[(size_t)BHT*SEQ*128];  // [bh][s][r|i]
__device__ unsigned short g_Qlo[(size_t)BHT*SEQ*128];
__device__ unsigned short g_Khi[(size_t)BHT*SEQ*128];
__device__ unsigned short g_Klo[(size_t)BHT*SEQ*128];
__device__ float          g_V [(size_t)BHT*SEQ*128];   // [bh][s][r(64)|i(64)] fp32
__device__ unsigned short g_VThi[(size_t)BHT*128*SEQ]; // [bh][d(r|i)][s]
__device__ unsigned short g_VTlo[(size_t)BHT*128*SEQ];
__device__ float          g_S  [(size_t)BHT*SEQ*SEQ];  // scores fp32, 512 MB
__device__ unsigned short g_Phi[(size_t)BHT*SEQ*SEQ];  // softmax hi, 256 MB
__device__ unsigned short g_Plo[(size_t)BHT*SEQ*SEQ];  // softmax lo, 256 MB

// ---------------------------- helpers --------------------------------------
__device__ __forceinline__ unsigned smem_u32(const void* p) {
    unsigned a;
    asm("{ .reg .u64 t; cvta.to.shared.u64 t, %1; cvt.u32.u64 %0, t; }"
        : "=r"(a) : "l"(p));
    return a;
}
__device__ __forceinline__ void ldm_x4(unsigned* r, unsigned addr) {
    asm volatile("ldmatrix.sync.aligned.m8n8.x4.shared.b16 {%0,%1,%2,%3}, [%4];"
                 : "=r"(r[0]), "=r"(r[1]), "=r"(r[2]), "=r"(r[3]) : "r"(addr));
}
__device__ __forceinline__ void mma_bf16(float* c, const unsigned* a,
                                         unsigned b0, unsigned b1) {
    asm volatile(
        "mma.sync.aligned.m16n8k16.row.col.f32.bf16.bf16.f32 "
        "{%0,%1,%2,%3}, {%4,%5,%6,%7}, {%8,%9}, {%0,%1,%2,%3};"
        : "+f"(c[0]), "+f"(c[1]), "+f"(c[2]), "+f"(c[3])
        : "r"(a[0]), "r"(a[1]), "r"(a[2]), "r"(a[3]), "r"(b0), "r"(b1));
}
__device__ __forceinline__ void split2(float x, float y, unsigned& hi, unsigned& lo) {
    __nv_bfloat16 hx = __float2bfloat16(x), hy = __float2bfloat16(y);
    float rx = x - __bfloat162float(hx), ry = y - __bfloat162float(hy);
    __nv_bfloat16 lx = __float2bfloat16(rx), ly = __float2bfloat16(ry);
    hi = ((unsigned)__bfloat16_as_ushort(hy) << 16) | __bfloat16_as_ushort(hx);
    lo = ((unsigned)__bfloat16_as_ushort(ly) << 16) | __bfloat16_as_ushort(lx);
}
__device__ __forceinline__ void cp16(unsigned sdst, const void* gsrc) {
    asm volatile("cp.async.cg.shared.global [%0], [%1], 16;"
                 :: "r"(sdst), "l"(__cvta_generic_to_global(gsrc)));
}
// stage one 128-row x 64B (k32) tile slice into SMEM (stride 80B, 2 rows/thread)
__device__ __forceinline__ void tile_load(unsigned sdst, const char* src,
                                          size_t stride, int rrow, int rc) {
    cp16(sdst + rrow*80 + rc,      src + (size_t)rrow*stride + rc);
    cp16(sdst + (rrow+64)*80 + rc, src + (size_t)(rrow+64)*stride + rc);
}
// fused k32 chunk: acc += Ahi.Bhi + Alo.Bhi + Ahi.Blo   (128x128 warp-tiled)
__device__ __forceinline__ void fused_chunk(unsigned sAh, unsigned sAl,
                                            unsigned sBh, unsigned sBl,
                                            int wm, int wn, int lane,
                                            float acc[2][8][4]) {
    const int mtx = lane >> 3, rowi = lane & 7;
    #pragma unroll
    for (int s = 0; s < 2; s++) {
        const unsigned aoff = (wm*32 + (lane & 15))*80 + ((lane >> 4)*8 + s*16)*2;
        unsigned ah[2][4], al[2][4];
        ldm_x4(ah[0], sAh + aoff);
        ldm_x4(ah[1], sAh + aoff + 16*80);
        ldm_x4(al[0], sAl + aoff);
        ldm_x4(al[1], sAl + aoff + 16*80);
        const unsigned boff = (wn*64 + ((mtx >> 1) << 3) + rowi)*80
                            + (s*16 + ((mtx & 1) << 3))*2;
        {   // B = hi: hi.hi and lo.hi
            unsigned b_[8][2];
            #pragma unroll
            for (int np = 0; np < 4; np++) {
                unsigned r[4];
                ldm_x4(r, sBh + boff + np*16*80);
                b_[np*2+0][0]=r[0]; b_[np*2+0][1]=r[1];
                b_[np*2+1][0]=r[2]; b_[np*2+1][1]=r[3];
            }
            #pragma unroll
            for (int mi = 0; mi < 2; mi++)
                #pragma unroll
                for (int nj = 0; nj < 8; nj++)
                    mma_bf16(acc[mi][nj], ah[mi], b_[nj][0], b_[nj][1]);
            #pragma unroll
            for (int mi = 0; mi < 2; mi++)
                #pragma unroll
                for (int nj = 0; nj < 8; nj++)
                    mma_bf16(acc[mi][nj], al[mi], b_[nj][0], b_[nj][1]);
        }
        {   // B = lo: hi.lo
            unsigned b_[8][2];
            #pragma unroll
            for (int np = 0; np < 4; np++) {
                unsigned r[4];
                ldm_x4(r, sBl + boff + np*16*80);
                b_[np*2+0][0]=r[0]; b_[np*2+0][1]=r[1];
                b_[np*2+1][0]=r[2]; b_[np*2+1][1]=r[3];
            }
            #pragma unroll
            for (int mi = 0; mi < 2; mi++)
                #pragma unroll
                for (int nj = 0; nj < 8; nj++)
                    mma_bf16(acc[mi][nj], ah[mi], b_[nj][0], b_[nj][1]);
        }
    }
}
#define SMEM_FUSED 81920   // 2 buffers x 4 tiles x 10240 B

// ---------------------------------------------------------------------------
// pack kernels (unchanged)
// ---------------------------------------------------------------------------
__global__ void pack_x(const float* __restrict__ xr, const float* __restrict__ xi)
{
    int idx = blockIdx.x * 256 + threadIdx.x;
    int m = idx >> 11, n = idx & 2047;
    float v = (n < 1024) ? xr[(size_t)m*1024 + n] : xi[(size_t)m*1024 + n - 1024];
    __nv_bfloat16 hi = __float2bfloat16(v);
    float lo = v - __bfloat162float(hi);
    g_Xhi[idx] = __bfloat16_as_ushort(hi);
    g_Xlo[idx] = __bfloat16_as_ushort(__float2bfloat16(lo));
}

__global__ void pack_w(const float* __restrict__ Wr, const float* __restrict__ Wi,
                       int n_offset)
{
    __shared__ float s[32*33];
    const int t = threadIdx.x;
    const int nl0 = blockIdx.x << 5;
    const int k0  = blockIdx.y << 5;
    const int comp = nl0 >> 10;
    const int j0 = nl0 & 1023;

    const float* src; float sgn = 1.0f; int kr0;
    if (k0 < 1024) { kr0 = k0; src = comp ? Wi : Wr; }
    else { kr0 = k0 - 1024; if (comp) src = Wr; else { src = Wi; sgn = -1.0f; } }

    #pragma unroll
    for (int p = 0; p < 4; p++) {
        int e = p*256 + t, kr = e >> 5, jc = e & 31;
        s[kr*33 + jc] = src[(size_t)(kr0 + kr)*1024 + j0 + jc] * sgn;
    }
    __syncthreads();
    #pragma unroll
    for (int p = 0; p < 4; p++) {
        int e = p*256 + t, nr = e >> 5, kc = e & 31;
        float v = s[kc*33 + nr];
        __nv_bfloat16 hi = __float2bfloat16(v);
        float lo = v - __bfloat162float(hi);
        size_t o = (size_t)(n_offset + nl0 + nr)*GK + k0 + kc;
        g_Whi[o] = __bfloat16_as_ushort(hi);
        g_Wlo[o] = __bfloat16_as_ushort(__float2bfloat16(lo));
    }
}

__global__ void pack_bias(const float* __restrict__ br, const float* __restrict__ bi,
                          int off)
{
    int n = blockIdx.x * 256 + threadIdx.x;
    g_bias[off + n] = (n < 1024) ? br[n] : bi[n - 1024];
}

// ---------------------------------------------------------------------------
// tgemm: fused split-bf16 HMMA GEMM over K=2048 (one sweep, 3 terms per chunk)
// MODE 0 (QKV): Q -> g_Qhi/lo, K -> g_Khi/lo (128-dim head layout), V fp32.
// MODE 1 (O):   write fp32 to Cout split by comp.
// ---------------------------------------------------------------------------
template<int MODE>
__global__ void __launch_bounds__(256, 2) tgemm(float* __restrict__ Cout, int nb_off)
{
    extern __shared__ char dsm[];
    const unsigned sb = smem_u32(dsm);

    const int t    = threadIdx.x;
    const int lane = t & 31;
    const int wid  = t >> 5;
    const int wm   = wid & 3;
    const int wn   = wid >> 2;
    const int m0   = blockIdx.y << 7;
    const int n0   = blockIdx.x << 7;
    const int rrow = t >> 2, rc = (t & 3) << 4;

    const char* Ah = (const char*)g_Xhi + (size_t)m0*(GK*2);
    const char* Al = (const char*)g_Xlo + (size_t)m0*(GK*2);
    const char* Bh = (const char*)(g_Whi + (size_t)nb_off*GK) + (size_t)n0*(GK*2);
    const char* Bl = (const char*)(g_Wlo + (size_t)nb_off*GK) + (size_t)n0*(GK*2);

    float acc[2][8][4];
    #pragma unroll
    for (int i = 0; i < 2; i++)
        #pragma unroll
        for (int j = 0; j < 8; j++)
            #pragma unroll
            for (int q = 0; q < 4; q++) acc[i][j][q] = 0.f;

    auto issue = [&](int cc, int buf) {
        const unsigned base = sb + buf*40960;
        const size_t ko = (size_t)cc*64;
        tile_load(base,         Ah + ko, GK*2, rrow, rc);
        tile_load(base+10240,   Al + ko, GK*2, rrow, rc);
        tile_load(base+20480,   Bh + ko, GK*2, rrow, rc);
        tile_load(base+30720,   Bl + ko, GK*2, rrow, rc);
        asm volatile("cp.async.commit_group;" ::: "memory");
    };

    issue(0, 0);
    for (int cc = 0; cc < 64; cc++) {
        const int buf = cc & 1;
        const bool pf = (cc + 1 < 64);
        if (pf) issue(cc + 1, buf ^ 1);
        if (pf) asm volatile("cp.async.wait_group 1;" ::: "memory");
        else    asm volatile("cp.async.wait_group 0;" ::: "memory");
        __syncthreads();
        const unsigned base = sb + buf*40960;
        fused_chunk(base, base+10240, base+20480, base+30720, wm, wn, lane, acc);
        __syncthreads();
    }

    const int r0 = m0 + wm*32 + (lane >> 2);
    const int cb = wn*64 + ((lane & 3) << 1);
    #pragma unroll
    for (int mi = 0; mi < 2; mi++)
        #pragma unroll
        for (int nj = 0; nj < 8; nj++) {
            const int n = n0 + cb + nj*8;
            const float bx = g_bias[nb_off + n];
            const float by = g_bias[nb_off + n + 1];
            float2 v0 = make_float2(acc[mi][nj][0] + bx, acc[mi][nj][1] + by);
            float2 v1 = make_float2(acc[mi][nj][2] + bx, acc[mi][nj][3] + by);
            const int row = r0 + mi*16;
            if (MODE == 0) {
                const int proj = n >> 11, rem = n & 2047;
                const int comp = rem >> 10, j = rem & 1023;
                const int h = j >> 6, d = j & 63;
                #pragma unroll
                for (int rr = 0; rr < 2; rr++) {
                    const int rw = row + rr*8;
                    const float2 v = rr ? v1 : v0;
                    const int bh = (rw >> 11)*NH + h, sq = rw & 2047;
                    if (proj == 0) {
                        unsigned hi, lo; split2(v.x, v.y, hi, lo);
                        size_t base = ((size_t)bh*SEQ + sq)*128 + comp*64 + d;
                        *(unsigned*)(g_Qhi + base) = hi;
                        *(unsigned*)(g_Qlo + base) = lo;
                    } else if (proj == 1) {
                        unsigned hi, lo; split2(v.x, v.y, hi, lo);
                        size_t base = ((size_t)bh*SEQ + sq)*128 + comp*64 + d;
                        *(unsigned*)(g_Khi + base) = hi;
                        *(unsigned*)(g_Klo + base) = lo;
                    } else {
                        *(float2*)(g_V + ((size_t)bh*SEQ + sq)*128 + comp*64 + d) = v;
                    }
                }
            } else {
                const int comp = n >> 10, j = n & 1023;
                float* dst = Cout + (size_t)comp*((size_t)MTOT*FEAT) + j;
                *(float2*)(dst + (size_t)row*FEAT)     = v0;
                *(float2*)(dst + (size_t)(row+8)*FEAT) = v1;
            }
        }
}

// ---------------------------------------------------------------------------
// pack_vt: g_V [bh][s][128] fp32 -> transposed bf16 hi/lo [bh][d128][s]
// ---------------------------------------------------------------------------
__global__ void pack_vt()
{
    __shared__ float sm[32*33];
    const int t = threadIdx.x;
    const int bh = blockIdx.z;
    const int c0 = blockIdx.y << 5;
    const int s0 = blockIdx.x << 5;

    #pragma unroll
    for (int p = 0; p < 4; p++) {
        int e = p*256 + t, r = e >> 5, c = e & 31;
        sm[r*33 + c] = g_V[((size_t)bh*SEQ + s0 + r)*128 + c0 + c];
    }
    __syncthreads();
    #pragma unroll
    for (int p = 0; p < 4; p++) {
        int e = p*256 + t, r = e >> 5, c = e & 31;
        float v = sm[c*33 + r];
        __nv_bfloat16 hi = __float2bfloat16(v);
        float lo = v - __bfloat162float(hi);
        size_t o = ((size_t)bh*128 + c0 + r)*SEQ + s0 + c;
        g_VThi[o] = __bfloat16_as_ushort(hi);
        g_VTlo[o] = __bfloat16_as_ushort(__float2bfloat16(lo));
    }
}

// ---------------------------------------------------------------------------
// scores_mma: S = 0.125*(Qhi.Khi + Qlo.Khi + Qhi.Klo) + mask   (K=128, fused)
// ---------------------------------------------------------------------------
__global__ void __launch_bounds__(256, 2) scores_mma(const float* __restrict__ mask)
{
    extern __shared__ char dsm[];
    const unsigned sb = smem_u32(dsm);

    const int t    = threadIdx.x;
    const int lane = t & 31;
    const int wid  = t >> 5;
    const int wm   = wid & 3;
    const int wn   = wid >> 2;
    const int bh   = blockIdx.z;
    const int m0   = blockIdx.y << 7;
    const int n0   = blockIdx.x << 7;
    const int rrow = t >> 2, rc = (t & 3) << 4;

    const char* Ah = (const char*)(g_Qhi + ((size_t)bh*SEQ + m0)*128);
    const char* Al = (const char*)(g_Qlo + ((size_t)bh*SEQ + m0)*128);
    const char* Bh = (const char*)(g_Khi + ((size_t)bh*SEQ + n0)*128);
    const char* Bl = (const char*)(g_Klo + ((size_t)bh*SEQ + n0)*128);

    float acc[2][8][4];
    #pragma unroll
    for (int i = 0; i < 2; i++)
        #pragma unroll
        for (int j = 0; j < 8; j++)
            #pragma unroll
            for (int q = 0; q < 4; q++) acc[i][j][q] = 0.f;

    auto issue = [&](int cc, int buf) {
        const unsigned base = sb + buf*40960;
        const size_t ko = (size_t)cc*64;
        tile_load(base,         Ah + ko, 256, rrow, rc);
        tile_load(base+10240,   Al + ko, 256, rrow, rc);
        tile_load(base+20480,   Bh + ko, 256, rrow, rc);
        tile_load(base+30720,   Bl + ko, 256, rrow, rc);
        asm volatile("cp.async.commit_group;" ::: "memory");
    };

    issue(0, 0);
    for (int cc = 0; cc < 4; cc++) {
        const int buf = cc & 1;
        const bool pf = (cc + 1 < 4);
        if (pf) issue(cc + 1, buf ^ 1);
        if (pf) asm volatile("cp.async.wait_group 1;" ::: "memory");
        else    asm volatile("cp.async.wait_group 0;" ::: "memory");
        __syncthreads();
        const unsigned base = sb + buf*40960;
        fused_chunk(base, base+10240, base+20480, base+30720, wm, wn, lane, acc);
        __syncthreads();
    }

    const int b = bh >> 4;
    const int r0 = m0 + wm*32 + (lane >> 2);
    const int cb = wn*64 + ((lane & 3) << 1);
    #pragma unroll
    for (int mi = 0; mi < 2; mi++)
        #pragma unroll
        for (int nj = 0; nj < 8; nj++) {
            const int n = n0 + cb + nj*8;
            const float mkx = (1.0f - mask[b*SEQ + n])   * -1e9f;
            const float mky = (1.0f - mask[b*SEQ + n+1]) * -1e9f;
            const int row = r0 + mi*16;
            float2 v0 = make_float2(acc[mi][nj][0]*0.125f + mkx,
                                    acc[mi][nj][1]*0.125f + mky);
            float2 v1 = make_float2(acc[mi][nj][2]*0.125f + mkx,
                                    acc[mi][nj][3]*0.125f + mky);
            *(float2*)(g_S + ((size_t)bh*SEQ + row)*SEQ + n)     = v0;
            *(float2*)(g_S + ((size_t)bh*SEQ + row + 8)*SEQ + n) = v1;
        }
}

// ---------------------------------------------------------------------------
// softmax: row softmax of g_S -> bf16 hi/lo P buffers (unchanged)
// ---------------------------------------------------------------------------
__global__ void __launch_bounds__(256) softmax_kernel()
{
    const size_t roff = (size_t)blockIdx.x * SEQ;
    const float* p = g_S + roff;
    const int t = threadIdx.x;
    float v[8];
    float mx = -1e30f;
    #pragma unroll
    for (int i = 0; i < 8; i++) { v[i] = p[t + (i << 8)]; mx = fmaxf(mx, v[i]); }
    #pragma unroll
    for (int o = 16; o > 0; o >>= 1) mx = fmaxf(mx, __shfl_xor_sync(0xffffffffu, mx, o));
    __shared__ float redm[8];
    __shared__ float reds[8];
    if ((t & 31) == 0) redm[t >> 5] = mx;
    __syncthreads();
    mx = redm[0];
    #pragma unroll
    for (int i = 1; i < 8; i++) mx = fmaxf(mx, redm[i]);

    float sum = 0.f;
    #pragma unroll
    for (int i = 0; i < 8; i++) { v[i] = __expf(v[i] - mx); sum += v[i]; }
    #pragma unroll
    for (int o = 16; o > 0; o >>= 1) sum += __shfl_xor_sync(0xffffffffu, sum, o);
    if ((t & 31) == 0) reds[t >> 5] = sum;
    __syncthreads();
    sum = 0.f;
    #pragma unroll
    for (int i = 0; i < 8; i++) sum += reds[i];
    const float inv = 1.0f / sum;
    #pragma unroll
    for (int i = 0; i < 8; i++) {
        float pv = v[i] * inv;
        __nv_bfloat16 hi = __float2bfloat16(pv);
        float lo = pv - __bfloat162float(hi);
        g_Phi[roff + t + (i << 8)] = __bfloat16_as_ushort(hi);
        g_Plo[roff + t + (i << 8)] = __bfloat16_as_ushort(__float2bfloat16(lo));
    }
}

// ---------------------------------------------------------------------------
// pv_mma: out = Phi.Vhi + Plo.Vhi + Phi.Vlo  (K=2048, fused single sweep)
// Writes o-proj input g_Xhi/g_Xlo directly: col = comp*1024 + h*64 + d.
// ---------------------------------------------------------------------------
__global__ void __launch_bounds__(256, 2) pv_mma()
{
    extern __shared__ char dsm[];
    const unsigned sb = smem_u32(dsm);

    const int t    = threadIdx.x;
    const int lane = t & 31;
    const int wid  = t >> 5;
    const int wm   = wid & 3;
    const int wn   = wid >> 2;
    const int bh   = blockIdx.z;
    const int m0   = blockIdx.y << 7;
    const int rrow = t >> 2, rc = (t & 3) << 4;

    const char* Ah = (const char*)(g_Phi + ((size_t)bh*SEQ + m0)*SEQ);
    const char* Al = (const char*)(g_Plo + ((size_t)bh*SEQ + m0)*SEQ);
    const char* Bh = (const char*)(g_VThi + (size_t)bh*128*SEQ);
    const char* Bl = (const char*)(g_VTlo + (size_t)bh*128*SEQ);

    float acc[2][8][4];
    #pragma unroll
    for (int i = 0; i < 2; i++)
        #pragma unroll
        for (int j = 0; j < 8; j++)
            #pragma unroll
            for (int q = 0; q < 4; q++) acc[i][j][q] = 0.f;

    auto issue = [&](int cc, int buf) {
        const unsigned base = sb + buf*40960;
        const size_t ko = (size_t)cc*64;
        tile_load(base,         Ah + ko, SEQ*2, rrow, rc);
        tile_load(base+10240,   Al + ko, SEQ*2, rrow, rc);
        tile_load(base+20480,   Bh + ko, SEQ*2, rrow, rc);
        tile_load(base+30720,   Bl + ko, SEQ*2, rrow, rc);
        asm volatile("cp.async.commit_group;" ::: "memory");
    };

    issue(0, 0);
    for (int cc = 0; cc < 64; cc++) {
        const int buf = cc & 1;
        const bool pf = (cc + 1 < 64);
        if (pf) issue(cc + 1, buf ^ 1);
        if (pf) asm volatile("cp.async.wait_group 1;" ::: "memory");
        else    asm volatile("cp.async.wait_group 0;" ::: "memory");
        __syncthreads();
        const unsigned base = sb + buf*40960;
        fused_chunk(base, base+10240, base+20480, base+30720, wm, wn, lane, acc);
        __syncthreads();
    }

    const int b = bh >> 4, h = bh & 15;
    const int r0 = m0 + wm*32 + (lane >> 2);
    const int cb = wn*64 + ((lane & 3) << 1);
    #pragma unroll
    for (int mi = 0; mi < 2; mi++)
        #pragma unroll
        for (int nj = 0; nj < 8; nj++) {
            const int n = cb + nj*8;
            const int comp = n >> 6, d = n & 63;
            const int col = comp*1024 + h*64 + d;
            const int row = r0 + mi*16;
            #pragma unroll
            for (int rr = 0; rr < 2; rr++) {
                const float x = acc[mi][nj][rr*2 + 0];
                const float y = acc[mi][nj][rr*2 + 1];
                unsigned hi, lo; split2(x, y, hi, lo);
                size_t base = (size_t)(b*SEQ + row + rr*8)*GK + col;
                *(unsigned*)(g_Xhi + base) = hi;
                *(unsigned*)(g_Xlo + base) = lo;
            }
        }
}

// ---------------------------------------------------------------------------
extern "C" void kernel_launch(void* const* d_in, const int* in_sizes, int n_in,
                              void* d_out, int out_size)
{
    (void)in_sizes; (void)n_in; (void)out_size;
    const float* x_r  = (const float*)d_in[0];
    const float* x_i  = (const float*)d_in[1];
    const float* mask = (const float*)d_in[2];
    const float* Wq_r = (const float*)d_in[3];
    const float* Wq_i = (const float*)d_in[4];
    const float* bq_r = (const float*)d_in[5];
    const float* bq_i = (const float*)d_in[6];
    const float* Wk_r = (const float*)d_in[7];
    const float* Wk_i = (const float*)d_in[8];
    const float* bk_r = (const float*)d_in[9];
    const float* bk_i = (const float*)d_in[10];
    const float* Wv_r = (const float*)d_in[11];
    const float* Wv_i = (const float*)d_in[12];
    const float* bv_r = (const float*)d_in[13];
    const float* bv_i = (const float*)d_in[14];
    const float* Wo_r = (const float*)d_in[15];
    const float* Wo_i = (const float*)d_in[16];
    const float* bo_r = (const float*)d_in[17];
    const float* bo_i = (const float*)d_in[18];
    float* out = (float*)d_out;

    cudaFuncSetAttribute(tgemm<0>, cudaFuncAttributeMaxDynamicSharedMemorySize, SMEM_FUSED);
    cudaFuncSetAttribute(tgemm<1>, cudaFuncAttributeMaxDynamicSharedMemorySize, SMEM_FUSED);
    cudaFuncSetAttribute(scores_mma, cudaFuncAttributeMaxDynamicSharedMemorySize, SMEM_FUSED);
    cudaFuncSetAttribute(pv_mma, cudaFuncAttributeMaxDynamicSharedMemorySize, SMEM_FUSED);

    pack_x<<<MTOT*GK/256, 256>>>(x_r, x_i);
    pack_w<<<dim3(64, 64), 256>>>(Wq_r, Wq_i, 0);
    pack_w<<<dim3(64, 64), 256>>>(Wk_r, Wk_i, 2048);
    pack_w<<<dim3(64, 64), 256>>>(Wv_r, Wv_i, 4096);
    pack_w<<<dim3(64, 64), 256>>>(Wo_r, Wo_i, 6144);
    pack_bias<<<8, 256>>>(bq_r, bq_i, 0);
    pack_bias<<<8, 256>>>(bk_r, bk_i, 2048);
    pack_bias<<<8, 256>>>(bv_r, bv_i, 4096);
    pack_bias<<<8, 256>>>(bo_r, bo_i, 6144);

    // QKV projection (fused HMMA) -> Q/K hi/lo (128-dim), V fp32
    tgemm<0><<<dim3(48, 32), 256, SMEM_FUSED>>>(nullptr, 0);
    pack_vt<<<dim3(SEQ/32, 4, BHT), 256>>>();

    // attention on HMMA (fused split precision)
    scores_mma<<<dim3(SEQ/128, SEQ/128, BHT), 256, SMEM_FUSED>>>(mask);
    softmax_kernel<<<BHT*SEQ, 256>>>();
    pv_mma<<<dim3(1, SEQ/128, BHT), 256, SMEM_FUSED>>>();

    // output projection (fused HMMA) -> d_out
    tgemm<1><<<dim3(16, 32), 256, SMEM_FUSED>>>(out, 6144);
}